// round 5
// baseline (speedup 1.0000x reference)
#include <cuda_runtime.h>
#include <cuda_bf16.h>
#include <cstdint>
#include <math.h>

#define BSZ 16
#define NC  1024
#define NT  2048
#define NTT (BSZ*NT)
#define XD  8
#define HID 256
#define HH  128
#define DD  384
#define NE  4
#define KM  288                     // MoE A' width: 8 tx + 256 r + 24 pad

// ---------------- scratch ----------------
__device__ float g_enc3[BSZ*HID];
__device__ float g_gd  [(size_t)NTT*NE];
__device__ float g_ebias[BSZ*HH];             // per-batch fps1 bias fold
__device__ float g_wgdf[KM*NE];               // decoder-gate folded weights [k][4]
__device__ float g_bgdf[NE];
__device__ float g_bmoe[NE*DD];               // MoE folded bias

// activations as bf16 hi/lo pairs
__device__ __nv_bfloat16 g_zh [(size_t)NTT*HID], g_zl [(size_t)NTT*HID];   // moe_out
__device__ __nv_bfloat16 g_fhh[(size_t)NTT*HH],  g_fhl[(size_t)NTT*HH];    // fps1 out
__device__ __nv_bfloat16 g_axh[(size_t)NTT*KM],  g_axl[(size_t)NTT*KM];    // [tx|r|pad]
__device__ __nv_bfloat16 g_z2h[(size_t)NTT*DD],  g_z2l[(size_t)NTT*DD];    // MoE out
__device__ __nv_bfloat16 g_h1h[(size_t)NTT*HID], g_h1l[(size_t)NTT*HID];
__device__ __nv_bfloat16 g_h2h[(size_t)NTT*HID], g_h2l[(size_t)NTT*HID];

// weights: bf16 hi/lo, [N,K] K-major
__device__ __nv_bfloat16 g_wf1h[128*256], g_wf1l[128*256];
__device__ __nv_bfloat16 g_wf2h[256*128], g_wf2l[256*128];
__device__ __nv_bfloat16 g_wmh [4*384*288], g_wml [4*384*288];
__device__ __nv_bfloat16 g_wd1h[256*384], g_wd1l[256*384];
__device__ __nv_bfloat16 g_wd2h[256*256], g_wd2l[256*256];

__device__ __forceinline__ void split_store(__nv_bfloat16* hi, __nv_bfloat16* lo,
                                            size_t idx, float v) {
    __nv_bfloat16 h = __float2bfloat16(v);
    hi[idx] = h;
    lo[idx] = __float2bfloat16(v - __bfloat162float(h));
}

// ---------------- weight prep: transpose + bf16 hi/lo split ----------------
__global__ __launch_bounds__(256) void prep_w(
    const float* __restrict__ W, __nv_bfloat16* __restrict__ hi,
    __nv_bfloat16* __restrict__ lo, int K, int N)
{
    for (int idx = blockIdx.x*256 + threadIdx.x; idx < K*N; idx += gridDim.x*256) {
        int n = idx / K, k = idx - n*K;
        float a = W[(size_t)k*N + n];
        split_store(hi, lo, idx, a);
    }
}

// MoE fold: B'[e][n][k]: k<8 -> (Wat@We_top)[k][n]; k<264 -> We[120+k][n]; pad 0.
// bias'[e][n] = bed[e][n] + bat@We_top[:,n]
__global__ __launch_bounds__(256) void prep_moe(
    const float* __restrict__ Wat, const float* __restrict__ bat,
    const float* __restrict__ Wed, const float* __restrict__ bed)
{
    int idx = blockIdx.x*256 + threadIdx.x;      // 0..1535 = e*384+n
    if (idx >= NE*DD) return;
    int e = idx / DD, n = idx - e*DD;
    const float* We = Wed + (size_t)e*DD*DD;     // [384,384]
    float watwe[8];
    #pragma unroll
    for (int x = 0; x < 8; x++) watwe[x] = 0.f;
    float bfold = 0.f;
    for (int j = 0; j < HH; j++) {
        float w = We[(size_t)j*DD + n];
        #pragma unroll
        for (int x = 0; x < 8; x++) watwe[x] = fmaf(Wat[x*HH + j], w, watwe[x]);
        bfold = fmaf(bat[j], w, bfold);
    }
    g_bmoe[e*DD + n] = bed[e*DD + n] + bfold;
    size_t base = (size_t)idx * KM;
    for (int k = 0; k < KM; k++) {
        float v = (k < 8) ? watwe[k] : (k < 264 ? We[(size_t)(120 + k)*DD + n] : 0.f);
        split_store(g_wmh, g_wml, base + k, v);
    }
}

// decoder-gate fold: Wg''[k][c]: k<8 -> (Wat@Wgd_top)[k][c]; k<264 -> Wgd[120+k][c]; pad 0
__global__ __launch_bounds__(384) void prep_dec(
    const float* __restrict__ Wat, const float* __restrict__ bat,
    const float* __restrict__ Wgd, const float* __restrict__ bgd)
{
    int idx = blockIdx.x*384 + threadIdx.x;      // (k,c): k=idx>>2, c=idx&3
    if (idx < NE) {
        float s = bgd[idx];
        for (int j = 0; j < HH; j++) s = fmaf(bat[j], Wgd[j*NE + idx], s);
        g_bgdf[idx] = s;
    }
    if (idx >= KM*NE) return;
    int k = idx >> 2, c = idx & 3;
    float v;
    if (k < 8) {
        v = 0.f;
        for (int j = 0; j < HH; j++) v = fmaf(Wat[k*HH + j], Wgd[j*NE + c], v);
    } else if (k < 264) v = Wgd[(120 + k)*NE + c];
    else v = 0.f;
    g_wgdf[idx] = v;
}

// per-batch fps1 bias: ebias[b][col] = bf1[col] + enc3[b] @ Wf1[0:256, col]
__global__ __launch_bounds__(256) void ebias_kernel(
    const float* __restrict__ Wf1, const float* __restrict__ bf1)
{
    int idx = blockIdx.x*256 + threadIdx.x;      // 0..2047
    int b = idx >> 7, col = idx & 127;
    float s = bf1[col];
    for (int k = 0; k < HID; k++) s = fmaf(g_enc3[b*HID + k], Wf1[k*HH + col], s);
    g_ebias[idx] = s;
}

// ---------------- mma.sync helpers ----------------
__device__ __forceinline__ uint32_t smem_u32(const void* p) {
    uint32_t a;
    asm("{ .reg .u64 t; cvta.to.shared.u64 t, %1; cvt.u32.u64 %0, t; }" : "=r"(a) : "l"(p));
    return a;
}
__device__ __forceinline__ void ldm_x4(uint32_t* r, uint32_t addr) {
    asm volatile("ldmatrix.sync.aligned.m8n8.x4.shared.b16 {%0,%1,%2,%3}, [%4];"
        : "=r"(r[0]), "=r"(r[1]), "=r"(r[2]), "=r"(r[3]) : "r"(addr));
}
__device__ __forceinline__ void mma16816(float* d, const uint32_t* a, const uint32_t* b) {
    asm volatile(
        "mma.sync.aligned.m16n8k16.row.col.f32.bf16.bf16.f32 "
        "{%0,%1,%2,%3}, {%4,%5,%6,%7}, {%8,%9}, {%0,%1,%2,%3};"
        : "+f"(d[0]), "+f"(d[1]), "+f"(d[2]), "+f"(d[3])
        : "r"(a[0]), "r"(a[1]), "r"(a[2]), "r"(a[3]), "r"(b[0]), "r"(b[1]));
}
__device__ __forceinline__ void cp16(uint32_t dst, const void* src) {
    asm volatile("cp.async.ca.shared.global [%0], [%1], 16;" :: "r"(dst), "l"(src));
}
__device__ __forceinline__ void cp_commit() { asm volatile("cp.async.commit_group;"); }
__device__ __forceinline__ void cp_wait0()  { asm volatile("cp.async.wait_group 0;"); }

#define LDS   40
#define TILEB 10240
#define OFF_AHI(s) ((s)*TILEB)
#define OFF_ALO(s) ((2+(s))*TILEB)
#define OFF_BHI(s) ((4+(s))*TILEB)
#define OFF_BLO(s) ((6+(s))*TILEB)
#define SMEM_GEMM  81920

// C pairs = act( A @ B^T + bias_eff ); all operands pre-split bf16 hi/lo.
// GATED: B expert-stacked, per-expert fp32 acc merged with gate (exact).
template<int GATED>
__global__ __launch_bounds__(256) void mma_gemm(
    const __nv_bfloat16* __restrict__ Ahi, const __nv_bfloat16* __restrict__ Alo,
    const __nv_bfloat16* __restrict__ Bhi, const __nv_bfloat16* __restrict__ Blo,
    const float* __restrict__ bias, const float* __restrict__ gate,
    __nv_bfloat16* __restrict__ Chi, __nv_bfloat16* __restrict__ Clo,
    int K, int ldc, int coff, int relu, int bbatch)
{
    extern __shared__ char smc[];
    __shared__ float sbias[NE*128];
    uint32_t smb = smem_u32(smc);
    int tid = threadIdx.x;
    int lane = tid & 31, warp = tid >> 5;
    int wm = warp >> 2, wn = warp & 3;
    int m0 = blockIdx.x * 128, n0 = blockIdx.y * 128;
    int Nfull = gridDim.y * 128;
    size_t bstride = (size_t)Nfull * K;
    const int nexp = GATED ? NE : 1;

    const float* bp = bias + (bbatch ? (size_t)(m0 >> 11) * Nfull : 0);
    for (int i = tid; i < nexp*128; i += 256)
        sbias[i] = bp[(size_t)(i >> 7) * Nfull + n0 + (i & 127)];

    float acc[4][4][4], accF[GATED ? 4 : 1][GATED ? 4 : 1][GATED ? 4 : 1];
    #pragma unroll
    for (int mi = 0; mi < 4; mi++)
        #pragma unroll
        for (int ni = 0; ni < 4; ni++)
            #pragma unroll
            for (int q = 0; q < 4; q++) acc[mi][ni][q] = 0.f;
    if (GATED) {
        #pragma unroll
        for (int mi = 0; mi < 4; mi++)
            #pragma unroll
            for (int ni = 0; ni < 4; ni++)
                #pragma unroll
                for (int q = 0; q < 4; q++) accF[mi][ni][q] = 0.f;
    }

    const int tiles = K >> 5;
    const int T = nexp * tiles;

    // cp.async mapping: 2 chunks of 16B per matrix per thread
    int crow[2], ccol[2];
    #pragma unroll
    for (int i = 0; i < 2; i++) { int c = tid + i*256; crow[i] = c >> 2; ccol[i] = (c & 3) << 3; }

    auto load_stage = [&](int s, int it2) {
        int e = it2 / tiles, k0 = (it2 - e*tiles) << 5;
        const __nv_bfloat16* Bh = Bhi + (size_t)e * bstride;
        const __nv_bfloat16* Bl = Blo + (size_t)e * bstride;
        #pragma unroll
        for (int i = 0; i < 2; i++) {
            uint32_t d = (uint32_t)(crow[i] * LDS + ccol[i]) * 2;
            size_t ao = (size_t)(m0 + crow[i]) * K + k0 + ccol[i];
            size_t bo = (size_t)(n0 + crow[i]) * K + k0 + ccol[i];
            cp16(smb + OFF_AHI(s) + d, &Ahi[ao]);
            cp16(smb + OFF_ALO(s) + d, &Alo[ao]);
            cp16(smb + OFF_BHI(s) + d, &Bh[bo]);
            cp16(smb + OFF_BLO(s) + d, &Bl[bo]);
        }
        cp_commit();
    };

    load_stage(0, 0);
    cp_wait0();
    __syncthreads();

    for (int it = 0; it < T; it++) {
        int s = it & 1, ns = s ^ 1;
        if (it + 1 < T) load_stage(ns, it + 1);

        uint32_t aH = smb + OFF_AHI(s), aL = smb + OFF_ALO(s);
        uint32_t bH = smb + OFF_BHI(s), bL = smb + OFF_BLO(s);
        #pragma unroll
        for (int ks = 0; ks < 2; ks++) {
            uint32_t bh[4][2], bl[4][2], r4[4];
            #pragma unroll
            for (int np = 0; np < 2; np++) {
                uint32_t off = (uint32_t)((wn*32 + np*16 + (lane & 15)) * LDS
                                          + ks*16 + (lane >> 4)*8) * 2;
                ldm_x4(r4, bH + off);
                bh[np*2+0][0] = r4[0]; bh[np*2+0][1] = r4[2];
                bh[np*2+1][0] = r4[1]; bh[np*2+1][1] = r4[3];
                ldm_x4(r4, bL + off);
                bl[np*2+0][0] = r4[0]; bl[np*2+0][1] = r4[2];
                bl[np*2+1][0] = r4[1]; bl[np*2+1][1] = r4[3];
            }
            uint32_t ah[4][4], al[4][4];
            #pragma unroll
            for (int mi = 0; mi < 4; mi++) {
                uint32_t off = (uint32_t)((wm*64 + mi*16 + (lane & 15)) * LDS
                                          + ks*16 + (lane >> 4)*8) * 2;
                ldm_x4(ah[mi], aH + off);
                ldm_x4(al[mi], aL + off);
            }
            #pragma unroll
            for (int mi = 0; mi < 4; mi++)
                #pragma unroll
                for (int ni = 0; ni < 4; ni++) {
                    mma16816(acc[mi][ni], ah[mi], bh[ni]);
                    mma16816(acc[mi][ni], ah[mi], bl[ni]);
                    mma16816(acc[mi][ni], al[mi], bh[ni]);
                }
        }
        // expert boundary: exact fp32 gate merge
        if (GATED && ((it + 1) % tiles == 0)) {
            int e = it / tiles;
            #pragma unroll
            for (int mi = 0; mi < 4; mi++) {
                int row0 = m0 + wm*64 + mi*16 + (lane >> 2);
                float gA = gate[(size_t)row0 * 4 + e];
                float gB = gate[(size_t)(row0 + 8) * 4 + e];
                #pragma unroll
                for (int ni = 0; ni < 4; ni++) {
                    accF[mi][ni][0] = fmaf(gA, acc[mi][ni][0], accF[mi][ni][0]);
                    accF[mi][ni][1] = fmaf(gA, acc[mi][ni][1], accF[mi][ni][1]);
                    accF[mi][ni][2] = fmaf(gB, acc[mi][ni][2], accF[mi][ni][2]);
                    accF[mi][ni][3] = fmaf(gB, acc[mi][ni][3], accF[mi][ni][3]);
                    acc[mi][ni][0] = acc[mi][ni][1] = acc[mi][ni][2] = acc[mi][ni][3] = 0.f;
                }
            }
        }
        if (it + 1 < T) cp_wait0();
        __syncthreads();
    }

    // epilogue -> bf16 hi/lo pairs
    #pragma unroll
    for (int mi = 0; mi < 4; mi++) {
        #pragma unroll
        for (int sub = 0; sub < 2; sub++) {
            int row = m0 + wm*64 + mi*16 + (lane >> 2) + sub*8;
            float4 g4 = make_float4(0.f, 0.f, 0.f, 0.f);
            if (GATED) g4 = *(const float4*)&gate[(size_t)row * 4];
            #pragma unroll
            for (int ni = 0; ni < 4; ni++) {
                int cl = wn*32 + ni*8 + (lane & 3)*2;
                float be0, be1;
                if (GATED) {
                    be0 = g4.x*sbias[cl]     + g4.y*sbias[128+cl]
                        + g4.z*sbias[256+cl] + g4.w*sbias[384+cl];
                    be1 = g4.x*sbias[cl+1]     + g4.y*sbias[128+cl+1]
                        + g4.z*sbias[256+cl+1] + g4.w*sbias[384+cl+1];
                } else { be0 = sbias[cl]; be1 = sbias[cl+1]; }
                float v0 = (GATED ? accF[mi][ni][sub*2+0] : acc[mi][ni][sub*2+0]) + be0;
                float v1 = (GATED ? accF[mi][ni][sub*2+1] : acc[mi][ni][sub*2+1]) + be1;
                if (relu) { v0 = fmaxf(v0, 0.f); v1 = fmaxf(v1, 0.f); }
                __nv_bfloat16 h0 = __float2bfloat16(v0), h1 = __float2bfloat16(v1);
                size_t idx = (size_t)row * ldc + coff + n0 + cl;
                *(__nv_bfloat162*)&Chi[idx] = __nv_bfloat162(h0, h1);
                *(__nv_bfloat162*)&Clo[idx] = __nv_bfloat162(
                    __float2bfloat16(v0 - __bfloat162float(h0)),
                    __float2bfloat16(v1 - __bfloat162float(h1)));
            }
        }
    }
}

// ---------------- enc3 ----------------
__global__ __launch_bounds__(256) void enc3_kernel(
    const float* __restrict__ cx, const float* __restrict__ cy,
    const float* __restrict__ Wp, const float* __restrict__ bp,
    const float* __restrict__ Wl, const float* __restrict__ bl)
{
    __shared__ float red[256*9];
    __shared__ float h0[HID];
    int b = blockIdx.x, tid = threadIdx.x;
    float l[9];
    #pragma unroll
    for (int x = 0; x < 9; x++) l[x] = 0.f;
    for (int c = tid; c < NC; c += 256) {
        #pragma unroll
        for (int x = 0; x < XD; x++) l[x] += cx[((size_t)b*NC + c)*XD + x];
        l[8] += cy[b*NC + c];
    }
    #pragma unroll
    for (int x = 0; x < 9; x++) red[tid*9 + x] = l[x];
    __syncthreads();
    for (int s = 128; s; s >>= 1) {
        if (tid < s) {
            #pragma unroll
            for (int x = 0; x < 9; x++) red[tid*9 + x] += red[(tid+s)*9 + x];
        }
        __syncthreads();
    }
    {
        int h = tid;
        float a = bp[h];
        #pragma unroll
        for (int x = 0; x < 9; x++) a = fmaf(red[x]*(1.f/NC), Wp[x*HID + h], a);
        h0[h] = a;
    }
    __syncthreads();
    {
        int h = tid;
        float a = bl[h];
        for (int k = 0; k < HID; k++) a = fmaf(h0[k], Wl[k*HID + h], a);
        g_enc3[b*HID + h] = a;
    }
}

// ---------------- per-target encoder: writes split moe_out + A' tx/pad ----------------
__global__ __launch_bounds__(256) void target_kernel(
    const float* __restrict__ cx, const float* __restrict__ cy,
    const float* __restrict__ txg,
    const float* __restrict__ Wee, const float* __restrict__ bee,
    const float* __restrict__ Wge, const float* __restrict__ bge)
{
    extern __shared__ float smf[];
    float* sc  = smf;
    float* sWe = sc  + NC*9;
    float* sbe = sWe + NE*9*HID;
    float* sWg = sbe + NE*HID;
    float* sbg = sWg + XD*NE;

    int b  = blockIdx.x >> 4;
    int t0 = (blockIdx.x & 15) << 7;
    int tid = threadIdx.x;

    for (int i = tid; i < NC*XD; i += 256) sc[(i>>3)*9 + (i&7)] = cx[(size_t)b*NC*XD + i];
    for (int i = tid; i < NC;    i += 256) sc[i*9 + 8] = cy[b*NC + i];
    for (int i = tid; i < NE*9*HID; i += 256) sWe[i] = Wee[i];
    for (int i = tid; i < NE*HID;   i += 256) sbe[i] = bee[i];
    if (tid < XD*NE) sWg[tid] = Wge[tid];
    if (tid < NE)    sbg[tid] = bge[tid];
    __syncthreads();

    int warp = tid >> 5, lane = tid & 31;
    for (int tt = warp; tt < 128; tt += 8) {
        int t = t0 + tt;
        size_t gt = (size_t)b*NT + t;
        float tx[XD];
        #pragma unroll
        for (int x = 0; x < XD; x++) tx[x] = txg[gt*XD + x];

        float acc[10];
        #pragma unroll
        for (int i = 0; i < 10; i++) acc[i] = 0.f;
        for (int c = lane; c < NC; c += 32) {
            const float* p = &sc[c*9];
            float d2 = 1e-12f;
            #pragma unroll
            for (int x = 0; x < XD; x++) { float d = tx[x]-p[x]; d2 = fmaf(d, d, d2); }
            float dist = d2 * __frsqrt_rn(d2);
            float w = __expf(-dist);
            acc[9] += w;
            #pragma unroll
            for (int x = 0; x < 9; x++) acc[x] = fmaf(w, p[x], acc[x]);
        }
        #pragma unroll
        for (int o = 16; o; o >>= 1) {
            #pragma unroll
            for (int i = 0; i < 10; i++) acc[i] += __shfl_xor_sync(0xffffffffu, acc[i], o);
        }
        float inv = 1.f/acc[9];
        float s[9];
        #pragma unroll
        for (int x = 0; x < 9; x++) s[x] = acc[x]*inv;

        float g[NE];
        #pragma unroll
        for (int e = 0; e < NE; e++) {
            float a = sbg[e];
            #pragma unroll
            for (int x = 0; x < XD; x++) a = fmaf(tx[x], sWg[x*NE + e], a);
            g[e] = a;
        }
        float gm = fmaxf(fmaxf(g[0],g[1]), fmaxf(g[2],g[3]));
        float gs = 0.f;
        #pragma unroll
        for (int e = 0; e < NE; e++) { g[e] = __expf(g[e]-gm); gs += g[e]; }
        float gi = 1.f/gs;
        #pragma unroll
        for (int e = 0; e < NE; e++) g[e] *= gi;

        #pragma unroll
        for (int j = 0; j < 8; j++) {
            int h = lane + 32*j;
            float o2 = 0.f;
            #pragma unroll
            for (int e = 0; e < NE; e++) {
                float a = sbe[e*HID + h];
                #pragma unroll
                for (int x = 0; x < 9; x++) a = fmaf(s[x], sWe[(e*9 + x)*HID + h], a);
                o2 = fmaf(g[e], a, o2);
            }
            split_store(g_zh, g_zl, gt*HID + h, o2);
        }
        // A' cols 0..7 = tx; pad cols 264..287 = 0
        if (lane < 8)  split_store(g_axh, g_axl, gt*KM + lane, tx[lane]);
        if (lane < 24) {
            g_axh[gt*KM + 264 + lane] = __float2bfloat16(0.f);
            g_axl[gt*KM + 264 + lane] = __float2bfloat16(0.f);
        }
    }
}

// ---------------- decoder gate (reads A' pairs, folded weights) ----------------
__global__ __launch_bounds__(256) void decgate_kernel()
{
    int warp = threadIdx.x >> 5, lane = threadIdx.x & 31;
    size_t gt = (size_t)blockIdx.x*8 + warp;
    float a0=0.f, a1=0.f, a2=0.f, a3=0.f;
    const float4* W4 = (const float4*)g_wgdf;
    for (int k = lane; k < KM; k += 32) {
        float z = __bfloat162float(g_axh[gt*KM + k]) + __bfloat162float(g_axl[gt*KM + k]);
        float4 w = W4[k];
        a0 = fmaf(z, w.x, a0); a1 = fmaf(z, w.y, a1);
        a2 = fmaf(z, w.z, a2); a3 = fmaf(z, w.w, a3);
    }
    #pragma unroll
    for (int o = 16; o; o >>= 1) {
        a0 += __shfl_xor_sync(0xffffffffu, a0, o);
        a1 += __shfl_xor_sync(0xffffffffu, a1, o);
        a2 += __shfl_xor_sync(0xffffffffu, a2, o);
        a3 += __shfl_xor_sync(0xffffffffu, a3, o);
    }
    a0 += g_bgdf[0]; a1 += g_bgdf[1]; a2 += g_bgdf[2]; a3 += g_bgdf[3];
    float m = fmaxf(fmaxf(a0,a1), fmaxf(a2,a3));
    float e0 = __expf(a0-m), e1 = __expf(a1-m), e2 = __expf(a2-m), e3 = __expf(a3-m);
    float inv = 1.f/(e0+e1+e2+e3);
    if (lane == 0) {
        g_gd[gt*4+0] = e0*inv; g_gd[gt*4+1] = e1*inv;
        g_gd[gt*4+2] = e2*inv; g_gd[gt*4+3] = e3*inv;
    }
}

// ---------------- head ----------------
__global__ __launch_bounds__(256) void head_kernel(
    const float* __restrict__ W3, const float* __restrict__ b3, float* __restrict__ out)
{
    int warp = threadIdx.x >> 5, lane = threadIdx.x & 31;
    size_t gt = (size_t)blockIdx.x*8 + warp;
    float a0=0.f, a1=0.f;
    const float2* W2 = (const float2*)W3;
    for (int k = lane; k < HID; k += 32) {
        float h = __bfloat162float(g_h2h[gt*HID + k]) + __bfloat162float(g_h2l[gt*HID + k]);
        float2 w = W2[k];
        a0 = fmaf(h, w.x, a0); a1 = fmaf(h, w.y, a1);
    }
    #pragma unroll
    for (int o = 16; o; o >>= 1) {
        a0 += __shfl_xor_sync(0xffffffffu, a0, o);
        a1 += __shfl_xor_sync(0xffffffffu, a1, o);
    }
    if (lane == 0) {
        float mu = a0 + b3[0];
        float x  = a1 + b3[1];
        float sp = fmaxf(x, 0.f) + log1pf(__expf(-fabsf(x)));
        out[gt]       = mu;
        out[NTT + gt] = 0.1f + 0.9f*sp;
    }
}

// ---------------- Moran k-NN lag ----------------
__global__ __launch_bounds__(256) void moran_kernel(
    const float* __restrict__ txg, const float* __restrict__ tyg, float* __restrict__ out)
{
    extern __shared__ float smf[];
    float* st  = smf;
    float* sy  = st + NT*9;
    float* smu = sy + NT;
    int b  = blockIdx.x >> 4;
    int t0 = (blockIdx.x & 15) << 7;
    int tid = threadIdx.x;

    for (int i = tid; i < NT*XD; i += 256) st[(i>>3)*9 + (i&7)] = txg[(size_t)b*NT*XD + i];
    for (int i = tid; i < NT; i += 256) { sy[i] = tyg[b*NT + i]; smu[i] = out[b*NT + i]; }
    __syncthreads();
    for (int i = tid; i < NT; i += 256) {
        float n = 0.f;
        #pragma unroll
        for (int x = 0; x < XD; x++) { float v = st[i*9 + x]; n = fmaf(v, v, n); }
        st[i*9 + 8] = n;
    }
    __syncthreads();

    int warp = tid >> 5, lane = tid & 31;
    for (int tt = warp; tt < 128; tt += 8) {
        int t = t0 + tt;
        float tx[XD];
        #pragma unroll
        for (int x = 0; x < XD; x++) tx[x] = st[t*9 + x];
        float tn = st[t*9 + 8];

        float bd0=INFINITY,bd1=INFINITY,bd2=INFINITY,bd3=INFINITY,bd4=INFINITY;
        int   bi0=0,bi1=0,bi2=0,bi3=0,bi4=0;
        for (int c = lane; c < NT; c += 32) {
            if (c == t) continue;
            const float* p = &st[c*9];
            float dot = 0.f;
            #pragma unroll
            for (int x = 0; x < XD; x++) dot = fmaf(tx[x], p[x], dot);
            float d2 = tn + p[8] - 2.f*dot;
            d2 = fmaxf(d2, 0.f) + 1e-12f;
            if (d2 < bd4) {
                bd4 = d2; bi4 = c;
                if (bd4 < bd3) { float td=bd3; bd3=bd4; bd4=td; int ti=bi3; bi3=bi4; bi4=ti; }
                if (bd3 < bd2) { float td=bd2; bd2=bd3; bd3=td; int ti=bi2; bi2=bi3; bi3=ti; }
                if (bd2 < bd1) { float td=bd1; bd1=bd2; bd2=td; int ti=bi1; bi1=bi2; bi2=ti; }
                if (bd1 < bd0) { float td=bd0; bd0=bd1; bd1=td; int ti=bi0; bi0=bi1; bi1=ti; }
            }
        }
        float seld[5]; int seli[5];
        #pragma unroll
        for (int r = 0; r < 5; r++) {
            float rd = bd0; int ri = bi0; int rl = lane;
            #pragma unroll
            for (int o = 16; o; o >>= 1) {
                float od = __shfl_xor_sync(0xffffffffu, rd, o);
                int   oi = __shfl_xor_sync(0xffffffffu, ri, o);
                int   ol = __shfl_xor_sync(0xffffffffu, rl, o);
                if (od < rd || (od == rd && oi < ri)) { rd = od; ri = oi; rl = ol; }
            }
            seld[r] = rd; seli[r] = ri;
            if (lane == rl) {
                bd0=bd1; bi0=bi1; bd1=bd2; bi1=bi2; bd2=bd3; bi2=bi3;
                bd3=bd4; bi3=bi4; bd4=INFINITY; bi4=0x7fffffff;
            }
        }
        if (lane == 0) {
            float w[5], ws = 0.f;
            #pragma unroll
            for (int r = 0; r < 5; r++) { w[r] = __expf(-0.1f*sqrtf(seld[r])); ws += w[r]; }
            float inv = 1.f/ws;
            float ly = 0.f, lm = 0.f;
            #pragma unroll
            for (int r = 0; r < 5; r++) {
                float wr = w[r]*inv;
                ly = fmaf(wr, sy[seli[r]],  ly);
                lm = fmaf(wr, smu[seli[r]], lm);
            }
            size_t gt = (size_t)b*NT + t;
            out[2*(size_t)NTT + gt] = ly;
            out[3*(size_t)NTT + gt] = lm;
        }
    }
}

// ---------------- launch ----------------
extern "C" void kernel_launch(void* const* d_in, const int* in_sizes, int n_in,
                              void* d_out, int out_size)
{
    const float* cx   = (const float*)d_in[0];
    const float* cy   = (const float*)d_in[1];
    const float* txp  = (const float*)d_in[2];
    const float* typ  = (const float*)d_in[3];
    const float* Wge  = (const float*)d_in[4];
    const float* bge  = (const float*)d_in[5];
    const float* Wee  = (const float*)d_in[6];
    const float* bee  = (const float*)d_in[7];
    const float* Wp3  = (const float*)d_in[8];
    const float* bp3  = (const float*)d_in[9];
    const float* Wlin = (const float*)d_in[10];
    const float* blin = (const float*)d_in[11];
    const float* Wf1  = (const float*)d_in[12];
    const float* bf1  = (const float*)d_in[13];
    const float* Wf2  = (const float*)d_in[14];
    const float* bf2  = (const float*)d_in[15];
    const float* Wat  = (const float*)d_in[16];
    const float* bat  = (const float*)d_in[17];
    const float* Wgd  = (const float*)d_in[18];
    const float* bgd  = (const float*)d_in[19];
    const float* Wed  = (const float*)d_in[20];
    const float* bed  = (const float*)d_in[21];
    const float* Wd1  = (const float*)d_in[22];
    const float* bd1  = (const float*)d_in[23];
    const float* Wd2  = (const float*)d_in[24];
    const float* bd2  = (const float*)d_in[25];
    const float* Wd3  = (const float*)d_in[26];
    const float* bd3  = (const float*)d_in[27];
    float* out = (float*)d_out;

    float *p_gd, *p_ebias, *p_bmoe;
    cudaGetSymbolAddress((void**)&p_gd,    g_gd);
    cudaGetSymbolAddress((void**)&p_ebias, g_ebias);
    cudaGetSymbolAddress((void**)&p_bmoe,  g_bmoe);
    __nv_bfloat16 *zh,*zl,*fhh,*fhl,*axh,*axl,*z2h,*z2l,*h1h,*h1l,*h2h,*h2l;
    cudaGetSymbolAddress((void**)&zh,  g_zh);  cudaGetSymbolAddress((void**)&zl,  g_zl);
    cudaGetSymbolAddress((void**)&fhh, g_fhh); cudaGetSymbolAddress((void**)&fhl, g_fhl);
    cudaGetSymbolAddress((void**)&axh, g_axh); cudaGetSymbolAddress((void**)&axl, g_axl);
    cudaGetSymbolAddress((void**)&z2h, g_z2h); cudaGetSymbolAddress((void**)&z2l, g_z2l);
    cudaGetSymbolAddress((void**)&h1h, g_h1h); cudaGetSymbolAddress((void**)&h1l, g_h1l);
    cudaGetSymbolAddress((void**)&h2h, g_h2h); cudaGetSymbolAddress((void**)&h2l, g_h2l);
    __nv_bfloat16 *wf1h,*wf1l,*wf2h,*wf2l,*wmh,*wml,*wd1h,*wd1l,*wd2h,*wd2l;
    cudaGetSymbolAddress((void**)&wf1h, g_wf1h); cudaGetSymbolAddress((void**)&wf1l, g_wf1l);
    cudaGetSymbolAddress((void**)&wf2h, g_wf2h); cudaGetSymbolAddress((void**)&wf2l, g_wf2l);
    cudaGetSymbolAddress((void**)&wmh,  g_wmh);  cudaGetSymbolAddress((void**)&wml,  g_wml);
    cudaGetSymbolAddress((void**)&wd1h, g_wd1h); cudaGetSymbolAddress((void**)&wd1l, g_wd1l);
    cudaGetSymbolAddress((void**)&wd2h, g_wd2h); cudaGetSymbolAddress((void**)&wd2l, g_wd2l);

    const int smem_t = (NC*9 + NE*9*HID + NE*HID + XD*NE + NE)*4;
    const int smem_m = (NT*9 + NT + NT)*4;
    cudaFuncSetAttribute(target_kernel, cudaFuncAttributeMaxDynamicSharedMemorySize, smem_t);
    cudaFuncSetAttribute(moran_kernel,  cudaFuncAttributeMaxDynamicSharedMemorySize, smem_m);
    cudaFuncSetAttribute(mma_gemm<0>,   cudaFuncAttributeMaxDynamicSharedMemorySize, SMEM_GEMM);
    cudaFuncSetAttribute(mma_gemm<1>,   cudaFuncAttributeMaxDynamicSharedMemorySize, SMEM_GEMM);

    // weight prep
    prep_w<<<128, 256>>>(Wf1 + 256*HH, wf1h, wf1l, 256, 128);   // fps1 moe-half only
    prep_w<<<128, 256>>>(Wf2, wf2h, wf2l, 128, 256);
    prep_w<<<384, 256>>>(Wd1, wd1h, wd1l, 384, 256);
    prep_w<<<256, 256>>>(Wd2, wd2h, wd2l, 256, 256);
    prep_moe<<<6, 256>>>(Wat, bat, Wed, bed);
    prep_dec<<<3, 384>>>(Wat, bat, Wgd, bgd);

    enc3_kernel<<<BSZ, 256>>>(cx, cy, Wp3, bp3, Wlin, blin);
    ebias_kernel<<<8, 256>>>(Wf1, bf1);
    target_kernel<<<256, 256, smem_t>>>(cx, cy, txp, Wee, bee, Wge, bge);
    // fps1: relu(moe @ Wf1_bot + ebias[b]) ; K=256
    mma_gemm<0><<<dim3(256,1), 256, SMEM_GEMM>>>(zh, zl, wf1h, wf1l, p_ebias, nullptr,
                                                 fhh, fhl, 256, 128, 0, 1, 1);
    // fps2: r -> A'[:,8:264] ; K=128
    mma_gemm<0><<<dim3(256,2), 256, SMEM_GEMM>>>(fhh, fhl, wf2h, wf2l, bf2, nullptr,
                                                 axh, axl, 128, KM, 8, 0, 0);
    decgate_kernel<<<NTT/8, 256>>>();
    // decoder MoE: K=288, 4 experts, exact fp32 gate merge
    mma_gemm<1><<<dim3(256,3), 256, SMEM_GEMM>>>(axh, axl, wmh, wml, p_bmoe, p_gd,
                                                 z2h, z2l, KM, DD, 0, 0, 0);
    mma_gemm<0><<<dim3(256,2), 256, SMEM_GEMM>>>(z2h, z2l, wd1h, wd1l, bd1, nullptr,
                                                 h1h, h1l, 384, 256, 0, 1, 0);
    mma_gemm<0><<<dim3(256,2), 256, SMEM_GEMM>>>(h1h, h1l, wd2h, wd2l, bd2, nullptr,
                                                 h2h, h2l, 256, 256, 0, 1, 0);
    head_kernel<<<NTT/8, 256>>>(Wd3, bd3, out);
    moran_kernel<<<256, 256, smem_m>>>(txp, typ, out);
}

// round 6
// speedup vs baseline: 1.0231x; 1.0231x over previous
#include <cuda_runtime.h>
#include <cuda_bf16.h>
#include <cstdint>
#include <math.h>

#define BSZ 16
#define NC  1024
#define NT  2048
#define NTT (BSZ*NT)
#define XD  8
#define HID 256
#define HH  128
#define DD  384
#define NE  4
#define KM  288                     // MoE A' width: 8 tx + 256 r + 24 pad

// ---------------- scratch ----------------
__device__ float g_enc3[BSZ*HID];
__device__ float g_gd  [(size_t)NTT*NE];
__device__ float g_ebias[BSZ*HH];
__device__ float g_wgdf[KM*NE];
__device__ float g_bgdf[NE];
__device__ float g_bmoe[NE*DD];

// activations as bf16 hi/lo pairs
__device__ __nv_bfloat16 g_zh [(size_t)NTT*HID], g_zl [(size_t)NTT*HID];
__device__ __nv_bfloat16 g_fhh[(size_t)NTT*HH],  g_fhl[(size_t)NTT*HH];
__device__ __nv_bfloat16 g_axh[(size_t)NTT*KM],  g_axl[(size_t)NTT*KM];
__device__ __nv_bfloat16 g_z2h[(size_t)NTT*DD],  g_z2l[(size_t)NTT*DD];
__device__ __nv_bfloat16 g_h1h[(size_t)NTT*HID], g_h1l[(size_t)NTT*HID];
__device__ __nv_bfloat16 g_h2h[(size_t)NTT*HID], g_h2l[(size_t)NTT*HID];

// weights: bf16 hi/lo, [N,K] K-major
__device__ __nv_bfloat16 g_wf1h[128*256], g_wf1l[128*256];
__device__ __nv_bfloat16 g_wf2h[256*128], g_wf2l[256*128];
__device__ __nv_bfloat16 g_wmh [4*384*288], g_wml [4*384*288];
__device__ __nv_bfloat16 g_wd1h[256*384], g_wd1l[256*384];
__device__ __nv_bfloat16 g_wd2h[256*256], g_wd2l[256*256];

__device__ __forceinline__ void split_store(__nv_bfloat16* hi, __nv_bfloat16* lo,
                                            size_t idx, float v) {
    __nv_bfloat16 h = __float2bfloat16(v);
    hi[idx] = h;
    lo[idx] = __float2bfloat16(v - __bfloat162float(h));
}

// ---------------- weight prep ----------------
__global__ __launch_bounds__(256) void prep_w(
    const float* __restrict__ W, __nv_bfloat16* __restrict__ hi,
    __nv_bfloat16* __restrict__ lo, int K, int N)
{
    for (int idx = blockIdx.x*256 + threadIdx.x; idx < K*N; idx += gridDim.x*256) {
        int n = idx / K, k = idx - n*K;
        split_store(hi, lo, idx, W[(size_t)k*N + n]);
    }
}

__global__ __launch_bounds__(256) void prep_moe(
    const float* __restrict__ Wat, const float* __restrict__ bat,
    const float* __restrict__ Wed, const float* __restrict__ bed)
{
    int idx = blockIdx.x*256 + threadIdx.x;
    if (idx >= NE*DD) return;
    int e = idx / DD, n = idx - e*DD;
    const float* We = Wed + (size_t)e*DD*DD;
    float watwe[8];
    #pragma unroll
    for (int x = 0; x < 8; x++) watwe[x] = 0.f;
    float bfold = 0.f;
    for (int j = 0; j < HH; j++) {
        float w = We[(size_t)j*DD + n];
        #pragma unroll
        for (int x = 0; x < 8; x++) watwe[x] = fmaf(Wat[x*HH + j], w, watwe[x]);
        bfold = fmaf(bat[j], w, bfold);
    }
    g_bmoe[e*DD + n] = bed[e*DD + n] + bfold;
    size_t base = (size_t)idx * KM;
    for (int k = 0; k < KM; k++) {
        float v = (k < 8) ? watwe[k] : (k < 264 ? We[(size_t)(120 + k)*DD + n] : 0.f);
        split_store(g_wmh, g_wml, base + k, v);
    }
}

__global__ __launch_bounds__(384) void prep_dec(
    const float* __restrict__ Wat, const float* __restrict__ bat,
    const float* __restrict__ Wgd, const float* __restrict__ bgd)
{
    int idx = blockIdx.x*384 + threadIdx.x;
    if (idx < NE) {
        float s = bgd[idx];
        for (int j = 0; j < HH; j++) s = fmaf(bat[j], Wgd[j*NE + idx], s);
        g_bgdf[idx] = s;
    }
    if (idx >= KM*NE) return;
    int k = idx >> 2, c = idx & 3;
    float v;
    if (k < 8) {
        v = 0.f;
        for (int j = 0; j < HH; j++) v = fmaf(Wat[k*HH + j], Wgd[j*NE + c], v);
    } else if (k < 264) v = Wgd[(120 + k)*NE + c];
    else v = 0.f;
    g_wgdf[idx] = v;
}

__global__ __launch_bounds__(256) void ebias_kernel(
    const float* __restrict__ Wf1, const float* __restrict__ bf1)
{
    int idx = blockIdx.x*256 + threadIdx.x;
    int b = idx >> 7, col = idx & 127;
    float s = bf1[col];
    for (int k = 0; k < HID; k++) s = fmaf(g_enc3[b*HID + k], Wf1[k*HH + col], s);
    g_ebias[idx] = s;
}

// ---------------- mma.sync helpers ----------------
__device__ __forceinline__ uint32_t smem_u32(const void* p) {
    uint32_t a;
    asm("{ .reg .u64 t; cvta.to.shared.u64 t, %1; cvt.u32.u64 %0, t; }" : "=r"(a) : "l"(p));
    return a;
}
__device__ __forceinline__ void ldm_x4(uint32_t* r, uint32_t addr) {
    asm volatile("ldmatrix.sync.aligned.m8n8.x4.shared.b16 {%0,%1,%2,%3}, [%4];"
        : "=r"(r[0]), "=r"(r[1]), "=r"(r[2]), "=r"(r[3]) : "r"(addr));
}
__device__ __forceinline__ void mma16816(float* d, const uint32_t* a, const uint32_t* b) {
    asm volatile(
        "mma.sync.aligned.m16n8k16.row.col.f32.bf16.bf16.f32 "
        "{%0,%1,%2,%3}, {%4,%5,%6,%7}, {%8,%9}, {%0,%1,%2,%3};"
        : "+f"(d[0]), "+f"(d[1]), "+f"(d[2]), "+f"(d[3])
        : "r"(a[0]), "r"(a[1]), "r"(a[2]), "r"(a[3]), "r"(b[0]), "r"(b[1]));
}
__device__ __forceinline__ void cp16(uint32_t dst, const void* src) {
    asm volatile("cp.async.ca.shared.global [%0], [%1], 16;" :: "r"(dst), "l"(src));
}
__device__ __forceinline__ void cp_commit() { asm volatile("cp.async.commit_group;"); }
__device__ __forceinline__ void cp_wait0()  { asm volatile("cp.async.wait_group 0;"); }

#define LDS   40
#define TILEB 10240
#define OFF_AHI(s) ((s)*TILEB)
#define OFF_ALO(s) ((2+(s))*TILEB)
#define OFF_BHI(s) ((4+(s))*TILEB)
#define OFF_BLO(s) ((6+(s))*TILEB)
#define SMEM_GEMM  81920

// C pairs = act( [rowscale] A @ B^T + bias_eff ); pre-split bf16 hi/lo operands.
// GATED: gate applied by scaling A rows during smem store (single accumulator bank).
template<int GATED>
__global__ __launch_bounds__(256) void mma_gemm(
    const __nv_bfloat16* __restrict__ Ahi, const __nv_bfloat16* __restrict__ Alo,
    const __nv_bfloat16* __restrict__ Bhi, const __nv_bfloat16* __restrict__ Blo,
    const float* __restrict__ bias, const float* __restrict__ gate,
    __nv_bfloat16* __restrict__ Chi, __nv_bfloat16* __restrict__ Clo,
    int K, int ldc, int coff, int relu, int bbatch)
{
    extern __shared__ char smc[];
    __shared__ float sbias[NE*128];
    uint32_t smb = smem_u32(smc);
    int tid = threadIdx.x;
    int lane = tid & 31, warp = tid >> 5;
    int wm = warp >> 2, wn = warp & 3;
    int m0 = blockIdx.x * 128, n0 = blockIdx.y * 128;
    int Nfull = gridDim.y * 128;
    size_t bstride = (size_t)Nfull * K;
    const int nexp = GATED ? NE : 1;

    const float* bp = bias + (bbatch ? (size_t)(m0 >> 11) * Nfull : 0);
    for (int i = tid; i < nexp*128; i += 256)
        sbias[i] = bp[(size_t)(i >> 7) * Nfull + n0 + (i & 127)];

    float acc[4][4][4];
    #pragma unroll
    for (int mi = 0; mi < 4; mi++)
        #pragma unroll
        for (int ni = 0; ni < 4; ni++)
            #pragma unroll
            for (int q = 0; q < 4; q++) acc[mi][ni][q] = 0.f;

    const int tiles = K >> 5;
    const int T = nexp * tiles;

    int crow[2], ccol[2];
    #pragma unroll
    for (int i = 0; i < 2; i++) { int c = tid + i*256; crow[i] = c >> 2; ccol[i] = (c & 3) << 3; }

    uint4 arh[2], arl[2]; float gv[2];

    // issue B (+A if non-gated) cp.async for stage s / iteration it2
    auto load_async = [&](int s, int it2) {
        int e = it2 / tiles, k0 = (it2 - e*tiles) << 5;
        const __nv_bfloat16* Bh = Bhi + (size_t)e * bstride;
        const __nv_bfloat16* Bl = Blo + (size_t)e * bstride;
        #pragma unroll
        for (int i = 0; i < 2; i++) {
            uint32_t d = (uint32_t)(crow[i] * LDS + ccol[i]) * 2;
            size_t bo = (size_t)(n0 + crow[i]) * K + k0 + ccol[i];
            cp16(smb + OFF_BHI(s) + d, &Bh[bo]);
            cp16(smb + OFF_BLO(s) + d, &Bl[bo]);
            if (!GATED) {
                size_t ao = (size_t)(m0 + crow[i]) * K + k0 + ccol[i];
                cp16(smb + OFF_AHI(s) + d, &Ahi[ao]);
                cp16(smb + OFF_ALO(s) + d, &Alo[ao]);
            }
        }
        cp_commit();
    };
    // LDG A pairs + gate for iteration it2 (GATED only)
    auto load_a_regs = [&](int it2) {
        int e = it2 / tiles, k0 = (it2 - e*tiles) << 5;
        #pragma unroll
        for (int i = 0; i < 2; i++) {
            size_t ao = (size_t)(m0 + crow[i]) * K + k0 + ccol[i];
            arh[i] = *(const uint4*)&Ahi[ao];
            arl[i] = *(const uint4*)&Alo[ao];
            gv[i]  = gate[(size_t)(m0 + crow[i]) * 4 + e];
        }
    };
    // scale+resplit+STS into stage s (GATED only)
    auto store_a = [&](int s) {
        #pragma unroll
        for (int i = 0; i < 2; i++) {
            const uint32_t* ph = (const uint32_t*)&arh[i];
            const uint32_t* pl = (const uint32_t*)&arl[i];
            uint32_t oh[4], ol[4];
            #pragma unroll
            for (int q = 0; q < 4; q++) {
                __nv_bfloat162 h2 = *(const __nv_bfloat162*)&ph[q];
                __nv_bfloat162 l2 = *(const __nv_bfloat162*)&pl[q];
                float v0 = gv[i] * (__bfloat162float(h2.x) + __bfloat162float(l2.x));
                float v1 = gv[i] * (__bfloat162float(h2.y) + __bfloat162float(l2.y));
                __nv_bfloat16 nh0 = __float2bfloat16(v0), nh1 = __float2bfloat16(v1);
                __nv_bfloat162 nh(nh0, nh1);
                __nv_bfloat162 nl(__float2bfloat16(v0 - __bfloat162float(nh0)),
                                  __float2bfloat16(v1 - __bfloat162float(nh1)));
                oh[q] = *(const uint32_t*)&nh;
                ol[q] = *(const uint32_t*)&nl;
            }
            uint32_t d = (uint32_t)(crow[i] * LDS + ccol[i]) * 2;
            *(uint4*)(smc + OFF_AHI(s) + d) = make_uint4(oh[0], oh[1], oh[2], oh[3]);
            *(uint4*)(smc + OFF_ALO(s) + d) = make_uint4(ol[0], ol[1], ol[2], ol[3]);
        }
    };

    // prologue
    load_async(0, 0);
    if (GATED) { load_a_regs(0); store_a(0); }
    cp_wait0();
    __syncthreads();

    for (int it = 0; it < T; it++) {
        int s = it & 1, ns = s ^ 1;
        if (it + 1 < T) {
            load_async(ns, it + 1);
            if (GATED) load_a_regs(it + 1);
        }

        uint32_t aH = smb + OFF_AHI(s), aL = smb + OFF_ALO(s);
        uint32_t bH = smb + OFF_BHI(s), bL = smb + OFF_BLO(s);
        #pragma unroll
        for (int ks = 0; ks < 2; ks++) {
            uint32_t bh[4][2], bl[4][2], r4[4];
            #pragma unroll
            for (int np = 0; np < 2; np++) {
                uint32_t off = (uint32_t)((wn*32 + np*16 + (lane & 15)) * LDS
                                          + ks*16 + (lane >> 4)*8) * 2;
                ldm_x4(r4, bH + off);
                bh[np*2+0][0] = r4[0]; bh[np*2+0][1] = r4[2];
                bh[np*2+1][0] = r4[1]; bh[np*2+1][1] = r4[3];
                ldm_x4(r4, bL + off);
                bl[np*2+0][0] = r4[0]; bl[np*2+0][1] = r4[2];
                bl[np*2+1][0] = r4[1]; bl[np*2+1][1] = r4[3];
            }
            uint32_t ah[4][4], al[4][4];
            #pragma unroll
            for (int mi = 0; mi < 4; mi++) {
                uint32_t off = (uint32_t)((wm*64 + mi*16 + (lane & 15)) * LDS
                                          + ks*16 + (lane >> 4)*8) * 2;
                ldm_x4(ah[mi], aH + off);
                ldm_x4(al[mi], aL + off);
            }
            #pragma unroll
            for (int mi = 0; mi < 4; mi++)
                #pragma unroll
                for (int ni = 0; ni < 4; ni++) {
                    mma16816(acc[mi][ni], ah[mi], bh[ni]);
                    mma16816(acc[mi][ni], ah[mi], bl[ni]);
                    mma16816(acc[mi][ni], al[mi], bh[ni]);
                }
        }
        if (it + 1 < T) {
            if (GATED) store_a(ns);
            cp_wait0();
        }
        __syncthreads();
    }

    // epilogue -> bf16 hi/lo pairs
    #pragma unroll
    for (int mi = 0; mi < 4; mi++) {
        #pragma unroll
        for (int sub = 0; sub < 2; sub++) {
            int row = m0 + wm*64 + mi*16 + (lane >> 2) + sub*8;
            float4 g4 = make_float4(0.f, 0.f, 0.f, 0.f);
            if (GATED) g4 = *(const float4*)&gate[(size_t)row * 4];
            #pragma unroll
            for (int ni = 0; ni < 4; ni++) {
                int cl = wn*32 + ni*8 + (lane & 3)*2;
                float be0, be1;
                if (GATED) {
                    be0 = g4.x*sbias[cl]     + g4.y*sbias[128+cl]
                        + g4.z*sbias[256+cl] + g4.w*sbias[384+cl];
                    be1 = g4.x*sbias[cl+1]     + g4.y*sbias[128+cl+1]
                        + g4.z*sbias[256+cl+1] + g4.w*sbias[384+cl+1];
                } else { be0 = sbias[cl]; be1 = sbias[cl+1]; }
                float v0 = acc[mi][ni][sub*2+0] + be0;
                float v1 = acc[mi][ni][sub*2+1] + be1;
                if (relu) { v0 = fmaxf(v0, 0.f); v1 = fmaxf(v1, 0.f); }
                __nv_bfloat16 h0 = __float2bfloat16(v0), h1 = __float2bfloat16(v1);
                size_t idx = (size_t)row * ldc + coff + n0 + cl;
                *(__nv_bfloat162*)&Chi[idx] = __nv_bfloat162(h0, h1);
                *(__nv_bfloat162*)&Clo[idx] = __nv_bfloat162(
                    __float2bfloat16(v0 - __bfloat162float(h0)),
                    __float2bfloat16(v1 - __bfloat162float(h1)));
            }
        }
    }
}

// ---------------- enc3 ----------------
__global__ __launch_bounds__(256) void enc3_kernel(
    const float* __restrict__ cx, const float* __restrict__ cy,
    const float* __restrict__ Wp, const float* __restrict__ bp,
    const float* __restrict__ Wl, const float* __restrict__ bl)
{
    __shared__ float red[256*9];
    __shared__ float h0[HID];
    int b = blockIdx.x, tid = threadIdx.x;
    float l[9];
    #pragma unroll
    for (int x = 0; x < 9; x++) l[x] = 0.f;
    for (int c = tid; c < NC; c += 256) {
        #pragma unroll
        for (int x = 0; x < XD; x++) l[x] += cx[((size_t)b*NC + c)*XD + x];
        l[8] += cy[b*NC + c];
    }
    #pragma unroll
    for (int x = 0; x < 9; x++) red[tid*9 + x] = l[x];
    __syncthreads();
    for (int s = 128; s; s >>= 1) {
        if (tid < s) {
            #pragma unroll
            for (int x = 0; x < 9; x++) red[tid*9 + x] += red[(tid+s)*9 + x];
        }
        __syncthreads();
    }
    {
        int h = tid;
        float a = bp[h];
        #pragma unroll
        for (int x = 0; x < 9; x++) a = fmaf(red[x]*(1.f/NC), Wp[x*HID + h], a);
        h0[h] = a;
    }
    __syncthreads();
    {
        int h = tid;
        float a = bl[h];
        for (int k = 0; k < HID; k++) a = fmaf(h0[k], Wl[k*HID + h], a);
        g_enc3[b*HID + h] = a;
    }
}

// ---------------- per-target encoder ----------------
__global__ __launch_bounds__(256) void target_kernel(
    const float* __restrict__ cx, const float* __restrict__ cy,
    const float* __restrict__ txg,
    const float* __restrict__ Wee, const float* __restrict__ bee,
    const float* __restrict__ Wge, const float* __restrict__ bge)
{
    extern __shared__ float smf[];
    float* sc  = smf;
    float* sWe = sc  + NC*9;
    float* sbe = sWe + NE*9*HID;
    float* sWg = sbe + NE*HID;
    float* sbg = sWg + XD*NE;

    int b  = blockIdx.x >> 4;
    int t0 = (blockIdx.x & 15) << 7;
    int tid = threadIdx.x;

    for (int i = tid; i < NC*XD; i += 256) sc[(i>>3)*9 + (i&7)] = cx[(size_t)b*NC*XD + i];
    for (int i = tid; i < NC;    i += 256) sc[i*9 + 8] = cy[b*NC + i];
    for (int i = tid; i < NE*9*HID; i += 256) sWe[i] = Wee[i];
    for (int i = tid; i < NE*HID;   i += 256) sbe[i] = bee[i];
    if (tid < XD*NE) sWg[tid] = Wge[tid];
    if (tid < NE)    sbg[tid] = bge[tid];
    __syncthreads();

    int warp = tid >> 5, lane = tid & 31;
    for (int tt = warp; tt < 128; tt += 8) {
        int t = t0 + tt;
        size_t gt = (size_t)b*NT + t;
        float tx[XD];
        #pragma unroll
        for (int x = 0; x < XD; x++) tx[x] = txg[gt*XD + x];

        float acc[10];
        #pragma unroll
        for (int i = 0; i < 10; i++) acc[i] = 0.f;
        for (int c = lane; c < NC; c += 32) {
            const float* p = &sc[c*9];
            float d2 = 1e-12f;
            #pragma unroll
            for (int x = 0; x < XD; x++) { float d = tx[x]-p[x]; d2 = fmaf(d, d, d2); }
            float dist = d2 * __frsqrt_rn(d2);
            float w = __expf(-dist);
            acc[9] += w;
            #pragma unroll
            for (int x = 0; x < 9; x++) acc[x] = fmaf(w, p[x], acc[x]);
        }
        #pragma unroll
        for (int o = 16; o; o >>= 1) {
            #pragma unroll
            for (int i = 0; i < 10; i++) acc[i] += __shfl_xor_sync(0xffffffffu, acc[i], o);
        }
        float inv = 1.f/acc[9];
        float s[9];
        #pragma unroll
        for (int x = 0; x < 9; x++) s[x] = acc[x]*inv;

        float g[NE];
        #pragma unroll
        for (int e = 0; e < NE; e++) {
            float a = sbg[e];
            #pragma unroll
            for (int x = 0; x < XD; x++) a = fmaf(tx[x], sWg[x*NE + e], a);
            g[e] = a;
        }
        float gm = fmaxf(fmaxf(g[0],g[1]), fmaxf(g[2],g[3]));
        float gs = 0.f;
        #pragma unroll
        for (int e = 0; e < NE; e++) { g[e] = __expf(g[e]-gm); gs += g[e]; }
        float gi = 1.f/gs;
        #pragma unroll
        for (int e = 0; e < NE; e++) g[e] *= gi;

        #pragma unroll
        for (int j = 0; j < 8; j++) {
            int h = lane + 32*j;
            float o2 = 0.f;
            #pragma unroll
            for (int e = 0; e < NE; e++) {
                float a = sbe[e*HID + h];
                #pragma unroll
                for (int x = 0; x < 9; x++) a = fmaf(s[x], sWe[(e*9 + x)*HID + h], a);
                o2 = fmaf(g[e], a, o2);
            }
            split_store(g_zh, g_zl, gt*HID + h, o2);
        }
        if (lane < 8)  split_store(g_axh, g_axl, gt*KM + lane, tx[lane]);
        if (lane < 24) {
            g_axh[gt*KM + 264 + lane] = __float2bfloat16(0.f);
            g_axl[gt*KM + 264 + lane] = __float2bfloat16(0.f);
        }
    }
}

// ---------------- decoder gate ----------------
__global__ __launch_bounds__(256) void decgate_kernel()
{
    int warp = threadIdx.x >> 5, lane = threadIdx.x & 31;
    size_t gt = (size_t)blockIdx.x*8 + warp;
    float a0=0.f, a1=0.f, a2=0.f, a3=0.f;
    const float4* W4 = (const float4*)g_wgdf;
    for (int k = lane; k < KM; k += 32) {
        float z = __bfloat162float(g_axh[gt*KM + k]) + __bfloat162float(g_axl[gt*KM + k]);
        float4 w = W4[k];
        a0 = fmaf(z, w.x, a0); a1 = fmaf(z, w.y, a1);
        a2 = fmaf(z, w.z, a2); a3 = fmaf(z, w.w, a3);
    }
    #pragma unroll
    for (int o = 16; o; o >>= 1) {
        a0 += __shfl_xor_sync(0xffffffffu, a0, o);
        a1 += __shfl_xor_sync(0xffffffffu, a1, o);
        a2 += __shfl_xor_sync(0xffffffffu, a2, o);
        a3 += __shfl_xor_sync(0xffffffffu, a3, o);
    }
    a0 += g_bgdf[0]; a1 += g_bgdf[1]; a2 += g_bgdf[2]; a3 += g_bgdf[3];
    float m = fmaxf(fmaxf(a0,a1), fmaxf(a2,a3));
    float e0 = __expf(a0-m), e1 = __expf(a1-m), e2 = __expf(a2-m), e3 = __expf(a3-m);
    float inv = 1.f/(e0+e1+e2+e3);
    if (lane == 0) {
        g_gd[gt*4+0] = e0*inv; g_gd[gt*4+1] = e1*inv;
        g_gd[gt*4+2] = e2*inv; g_gd[gt*4+3] = e3*inv;
    }
}

// ---------------- head ----------------
__global__ __launch_bounds__(256) void head_kernel(
    const float* __restrict__ W3, const float* __restrict__ b3, float* __restrict__ out)
{
    int warp = threadIdx.x >> 5, lane = threadIdx.x & 31;
    size_t gt = (size_t)blockIdx.x*8 + warp;
    float a0=0.f, a1=0.f;
    const float2* W2 = (const float2*)W3;
    for (int k = lane; k < HID; k += 32) {
        float h = __bfloat162float(g_h2h[gt*HID + k]) + __bfloat162float(g_h2l[gt*HID + k]);
        float2 w = W2[k];
        a0 = fmaf(h, w.x, a0); a1 = fmaf(h, w.y, a1);
    }
    #pragma unroll
    for (int o = 16; o; o >>= 1) {
        a0 += __shfl_xor_sync(0xffffffffu, a0, o);
        a1 += __shfl_xor_sync(0xffffffffu, a1, o);
    }
    if (lane == 0) {
        float mu = a0 + b3[0];
        float x  = a1 + b3[1];
        float sp = fmaxf(x, 0.f) + log1pf(__expf(-fabsf(x)));
        out[gt]       = mu;
        out[NTT + gt] = 0.1f + 0.9f*sp;
    }
}

// ---------------- Moran k-NN lag ----------------
__global__ __launch_bounds__(256) void moran_kernel(
    const float* __restrict__ txg, const float* __restrict__ tyg, float* __restrict__ out)
{
    extern __shared__ float smf[];
    float* st  = smf;
    float* sy  = st + NT*9;
    float* smu = sy + NT;
    int b  = blockIdx.x >> 4;
    int t0 = (blockIdx.x & 15) << 7;
    int tid = threadIdx.x;

    for (int i = tid; i < NT*XD; i += 256) st[(i>>3)*9 + (i&7)] = txg[(size_t)b*NT*XD + i];
    for (int i = tid; i < NT; i += 256) { sy[i] = tyg[b*NT + i]; smu[i] = out[b*NT + i]; }
    __syncthreads();
    for (int i = tid; i < NT; i += 256) {
        float n = 0.f;
        #pragma unroll
        for (int x = 0; x < XD; x++) { float v = st[i*9 + x]; n = fmaf(v, v, n); }
        st[i*9 + 8] = n;
    }
    __syncthreads();

    int warp = tid >> 5, lane = tid & 31;
    for (int tt = warp; tt < 128; tt += 8) {
        int t = t0 + tt;
        float tx[XD];
        #pragma unroll
        for (int x = 0; x < XD; x++) tx[x] = st[t*9 + x];
        float tn = st[t*9 + 8];

        float bd0=INFINITY,bd1=INFINITY,bd2=INFINITY,bd3=INFINITY,bd4=INFINITY;
        int   bi0=0,bi1=0,bi2=0,bi3=0,bi4=0;
        for (int c = lane; c < NT; c += 32) {
            if (c == t) continue;
            const float* p = &st[c*9];
            float dot = 0.f;
            #pragma unroll
            for (int x = 0; x < XD; x++) dot = fmaf(tx[x], p[x], dot);
            float d2 = tn + p[8] - 2.f*dot;
            d2 = fmaxf(d2, 0.f) + 1e-12f;
            if (d2 < bd4) {
                bd4 = d2; bi4 = c;
                if (bd4 < bd3) { float td=bd3; bd3=bd4; bd4=td; int ti=bi3; bi3=bi4; bi4=ti; }
                if (bd3 < bd2) { float td=bd2; bd2=bd3; bd3=td; int ti=bi2; bi2=bi3; bi3=ti; }
                if (bd2 < bd1) { float td=bd1; bd1=bd2; bd2=td; int ti=bi1; bi1=bi2; bi2=ti; }
                if (bd1 < bd0) { float td=bd0; bd0=bd1; bd1=td; int ti=bi0; bi0=bi1; bi1=ti; }
            }
        }
        float seld[5]; int seli[5];
        #pragma unroll
        for (int r = 0; r < 5; r++) {
            float rd = bd0; int ri = bi0; int rl = lane;
            #pragma unroll
            for (int o = 16; o; o >>= 1) {
                float od = __shfl_xor_sync(0xffffffffu, rd, o);
                int   oi = __shfl_xor_sync(0xffffffffu, ri, o);
                int   ol = __shfl_xor_sync(0xffffffffu, rl, o);
                if (od < rd || (od == rd && oi < ri)) { rd = od; ri = oi; rl = ol; }
            }
            seld[r] = rd; seli[r] = ri;
            if (lane == rl) {
                bd0=bd1; bi0=bi1; bd1=bd2; bi1=bi2; bd2=bd3; bi2=bi3;
                bd3=bd4; bi3=bi4; bd4=INFINITY; bi4=0x7fffffff;
            }
        }
        if (lane == 0) {
            float w[5], ws = 0.f;
            #pragma unroll
            for (int r = 0; r < 5; r++) { w[r] = __expf(-0.1f*sqrtf(seld[r])); ws += w[r]; }
            float inv = 1.f/ws;
            float ly = 0.f, lm = 0.f;
            #pragma unroll
            for (int r = 0; r < 5; r++) {
                float wr = w[r]*inv;
                ly = fmaf(wr, sy[seli[r]],  ly);
                lm = fmaf(wr, smu[seli[r]], lm);
            }
            size_t gt = (size_t)b*NT + t;
            out[2*(size_t)NTT + gt] = ly;
            out[3*(size_t)NTT + gt] = lm;
        }
    }
}

// ---------------- launch ----------------
extern "C" void kernel_launch(void* const* d_in, const int* in_sizes, int n_in,
                              void* d_out, int out_size)
{
    const float* cx   = (const float*)d_in[0];
    const float* cy   = (const float*)d_in[1];
    const float* txp  = (const float*)d_in[2];
    const float* typ  = (const float*)d_in[3];
    const float* Wge  = (const float*)d_in[4];
    const float* bge  = (const float*)d_in[5];
    const float* Wee  = (const float*)d_in[6];
    const float* bee  = (const float*)d_in[7];
    const float* Wp3  = (const float*)d_in[8];
    const float* bp3  = (const float*)d_in[9];
    const float* Wlin = (const float*)d_in[10];
    const float* blin = (const float*)d_in[11];
    const float* Wf1  = (const float*)d_in[12];
    const float* bf1  = (const float*)d_in[13];
    const float* Wf2  = (const float*)d_in[14];
    const float* bf2  = (const float*)d_in[15];
    const float* Wat  = (const float*)d_in[16];
    const float* bat  = (const float*)d_in[17];
    const float* Wgd  = (const float*)d_in[18];
    const float* bgd  = (const float*)d_in[19];
    const float* Wed  = (const float*)d_in[20];
    const float* bed  = (const float*)d_in[21];
    const float* Wd1  = (const float*)d_in[22];
    const float* bd1  = (const float*)d_in[23];
    const float* Wd2  = (const float*)d_in[24];
    const float* bd2  = (const float*)d_in[25];
    const float* Wd3  = (const float*)d_in[26];
    const float* bd3  = (const float*)d_in[27];
    float* out = (float*)d_out;

    float *p_gd, *p_ebias, *p_bmoe;
    cudaGetSymbolAddress((void**)&p_gd,    g_gd);
    cudaGetSymbolAddress((void**)&p_ebias, g_ebias);
    cudaGetSymbolAddress((void**)&p_bmoe,  g_bmoe);
    __nv_bfloat16 *zh,*zl,*fhh,*fhl,*axh,*axl,*z2h,*z2l,*h1h,*h1l,*h2h,*h2l;
    cudaGetSymbolAddress((void**)&zh,  g_zh);  cudaGetSymbolAddress((void**)&zl,  g_zl);
    cudaGetSymbolAddress((void**)&fhh, g_fhh); cudaGetSymbolAddress((void**)&fhl, g_fhl);
    cudaGetSymbolAddress((void**)&axh, g_axh); cudaGetSymbolAddress((void**)&axl, g_axl);
    cudaGetSymbolAddress((void**)&z2h, g_z2h); cudaGetSymbolAddress((void**)&z2l, g_z2l);
    cudaGetSymbolAddress((void**)&h1h, g_h1h); cudaGetSymbolAddress((void**)&h1l, g_h1l);
    cudaGetSymbolAddress((void**)&h2h, g_h2h); cudaGetSymbolAddress((void**)&h2l, g_h2l);
    __nv_bfloat16 *wf1h,*wf1l,*wf2h,*wf2l,*wmh,*wml,*wd1h,*wd1l,*wd2h,*wd2l;
    cudaGetSymbolAddress((void**)&wf1h, g_wf1h); cudaGetSymbolAddress((void**)&wf1l, g_wf1l);
    cudaGetSymbolAddress((void**)&wf2h, g_wf2h); cudaGetSymbolAddress((void**)&wf2l, g_wf2l);
    cudaGetSymbolAddress((void**)&wmh,  g_wmh);  cudaGetSymbolAddress((void**)&wml,  g_wml);
    cudaGetSymbolAddress((void**)&wd1h, g_wd1h); cudaGetSymbolAddress((void**)&wd1l, g_wd1l);
    cudaGetSymbolAddress((void**)&wd2h, g_wd2h); cudaGetSymbolAddress((void**)&wd2l, g_wd2l);

    const int smem_t = (NC*9 + NE*9*HID + NE*HID + XD*NE + NE)*4;
    const int smem_m = (NT*9 + NT + NT)*4;
    cudaFuncSetAttribute(target_kernel, cudaFuncAttributeMaxDynamicSharedMemorySize, smem_t);
    cudaFuncSetAttribute(moran_kernel,  cudaFuncAttributeMaxDynamicSharedMemorySize, smem_m);
    cudaFuncSetAttribute(mma_gemm<0>,   cudaFuncAttributeMaxDynamicSharedMemorySize, SMEM_GEMM);
    cudaFuncSetAttribute(mma_gemm<1>,   cudaFuncAttributeMaxDynamicSharedMemorySize, SMEM_GEMM);

    prep_w<<<128, 256>>>(Wf1 + 256*HH, wf1h, wf1l, 256, 128);
    prep_w<<<128, 256>>>(Wf2, wf2h, wf2l, 128, 256);
    prep_w<<<384, 256>>>(Wd1, wd1h, wd1l, 384, 256);
    prep_w<<<256, 256>>>(Wd2, wd2h, wd2l, 256, 256);
    prep_moe<<<6, 256>>>(Wat, bat, Wed, bed);
    prep_dec<<<3, 384>>>(Wat, bat, Wgd, bgd);

    enc3_kernel<<<BSZ, 256>>>(cx, cy, Wp3, bp3, Wlin, blin);
    ebias_kernel<<<8, 256>>>(Wf1, bf1);
    target_kernel<<<256, 256, smem_t>>>(cx, cy, txp, Wee, bee, Wge, bge);
    mma_gemm<0><<<dim3(256,1), 256, SMEM_GEMM>>>(zh, zl, wf1h, wf1l, p_ebias, nullptr,
                                                 fhh, fhl, 256, 128, 0, 1, 1);
    mma_gemm<0><<<dim3(256,2), 256, SMEM_GEMM>>>(fhh, fhl, wf2h, wf2l, bf2, nullptr,
                                                 axh, axl, 128, KM, 8, 0, 0);
    decgate_kernel<<<NTT/8, 256>>>();
    mma_gemm<1><<<dim3(256,3), 256, SMEM_GEMM>>>(axh, axl, wmh, wml, p_bmoe, p_gd,
                                                 z2h, z2l, KM, DD, 0, 0, 0);
    mma_gemm<0><<<dim3(256,2), 256, SMEM_GEMM>>>(z2h, z2l, wd1h, wd1l, bd1, nullptr,
                                                 h1h, h1l, 384, 256, 0, 1, 0);
    mma_gemm<0><<<dim3(256,2), 256, SMEM_GEMM>>>(h1h, h1l, wd2h, wd2l, bd2, nullptr,
                                                 h2h, h2l, 256, 256, 0, 1, 0);
    head_kernel<<<NTT/8, 256>>>(Wd3, bd3, out);
    moran_kernel<<<256, 256, smem_m>>>(txp, typ, out);
}

// round 7
// speedup vs baseline: 1.3428x; 1.3125x over previous
#include <cuda_runtime.h>
#include <cuda_fp16.h>
#include <cstdint>
#include <math.h>

#define BSZ 16
#define NC  1024
#define NT  2048
#define NTT (BSZ*NT)
#define XD  8
#define HID 256
#define HH  128
#define DD  384
#define NE  4

// ---------------- scratch ----------------
__device__ float g_enc3[BSZ*HID];
__device__ float g_z  [(size_t)NTT*512];
__device__ float g_fh [(size_t)NTT*HH];
__device__ float g_zd [(size_t)NTT*DD];
__device__ float g_gd [(size_t)NTT*NE];
__device__ float g_zd2[(size_t)NTT*DD];
__device__ float g_h1 [(size_t)NTT*HID];
__device__ float g_h2 [(size_t)NTT*HID];

// weights: single fp16, pre-transposed to [N,K] K-major
__device__ __half g_wf1[128*512];
__device__ __half g_wf2[256*128];
__device__ __half g_wm [4*384*384];
__device__ __half g_wd1[256*384];
__device__ __half g_wd2[256*256];

// ---------------- weight prep: transpose + fp16 round ----------------
__global__ __launch_bounds__(256) void prep_w(
    const float* __restrict__ W, __half* __restrict__ hi, int K, int N)
{
    int e = blockIdx.y;
    size_t base = (size_t)e*K*N;
    for (int idx = blockIdx.x*256 + threadIdx.x; idx < K*N; idx += gridDim.x*256) {
        int n = idx / K, k = idx - n*K;
        hi[base + idx] = __float2half_rn(W[base + (size_t)k*N + n]);
    }
}

// ---------------- mma.sync helpers (fp16 HMMA) ----------------
__device__ __forceinline__ uint32_t smem_u32(const void* p) {
    uint32_t a;
    asm("{ .reg .u64 t; cvta.to.shared.u64 t, %1; cvt.u32.u64 %0, t; }" : "=r"(a) : "l"(p));
    return a;
}
__device__ __forceinline__ void ldm_x4(uint32_t* r, uint32_t addr) {
    asm volatile("ldmatrix.sync.aligned.m8n8.x4.shared.b16 {%0,%1,%2,%3}, [%4];"
        : "=r"(r[0]), "=r"(r[1]), "=r"(r[2]), "=r"(r[3]) : "r"(addr));
}
__device__ __forceinline__ void mma16816(float* d, const uint32_t* a, const uint32_t* b) {
    asm volatile(
        "mma.sync.aligned.m16n8k16.row.col.f32.f16.f16.f32 "
        "{%0,%1,%2,%3}, {%4,%5,%6,%7}, {%8,%9}, {%0,%1,%2,%3};"
        : "+f"(d[0]), "+f"(d[1]), "+f"(d[2]), "+f"(d[3])
        : "r"(a[0]), "r"(a[1]), "r"(a[2]), "r"(a[3]), "r"(b[0]), "r"(b[1]));
}
__device__ __forceinline__ void cp16(uint32_t dst, const void* src) {
    asm volatile("cp.async.ca.shared.global [%0], [%1], 16;" :: "r"(dst), "l"(src));
}
__device__ __forceinline__ void cp_commit() { asm volatile("cp.async.commit_group;"); }
__device__ __forceinline__ void cp_wait0()  { asm volatile("cp.async.wait_group 0;"); }

// smem: fp16, row stride 40 elems (80B), 128x32 tiles
#define LDS   40
#define TILEB 10240
#define OFF_AHI(s) ((s)*TILEB)
#define OFF_ALO(s) ((2+(s))*TILEB)
#define OFF_BHI(s) ((4+(s))*TILEB)
#define SMEM_GEMM  61440

// C[M,Nfull](@ldc,coff) = act( rowscale(A) @ B^T + bias_eff )
// A fp32, split in-loop to exact fp16 hi/lo; B single fp16 [N,K], expert-stacked.
// gate!=null: A rows scaled by gate[row,e]; acc over experts; gated bias.
__global__ __launch_bounds__(256) void mma_gemm(
    const float* __restrict__ A, const __half* __restrict__ Bw,
    const float* __restrict__ bias, const float* __restrict__ gate,
    float* __restrict__ C,
    int K, int ldc, int coff, int nexp, int relu)
{
    extern __shared__ char smc[];
    __shared__ float sbias[NE*128];
    uint32_t smb = smem_u32(smc);
    int tid = threadIdx.x;
    int lane = tid & 31, warp = tid >> 5;
    int wm = warp >> 2, wn = warp & 3;          // 2x4 warps: 64x32 warp tile
    int m0 = blockIdx.x * 128, n0 = blockIdx.y * 128;
    int Nfull = gridDim.y * 128;
    size_t bstride = (size_t)Nfull * K;

    for (int i = tid; i < nexp*128; i += 256)
        sbias[i] = bias[(size_t)(i >> 7) * Nfull + n0 + (i & 127)];

    float acc[4][4][4];
    #pragma unroll
    for (int mi = 0; mi < 4; mi++)
        #pragma unroll
        for (int ni = 0; ni < 4; ni++)
            #pragma unroll
            for (int q = 0; q < 4; q++) acc[mi][ni][q] = 0.f;

    const int tiles = K >> 5;
    const int T = nexp * tiles;

    // A fp32: 4 chunks of float4 per thread
    int arow[4], acol[4];
    #pragma unroll
    for (int i = 0; i < 4; i++) { int c = tid + i*256; arow[i] = c >> 3; acol[i] = (c & 7) << 2; }
    // B fp16: 2 chunks of 16B per thread
    int brow[2], bcol[2];
    #pragma unroll
    for (int i = 0; i < 2; i++) { int c = tid + i*256; brow[i] = c >> 2; bcol[i] = (c & 3) << 3; }

    float4 ar[4]; float gv[4];

    auto load_b = [&](int s, int it2) {
        int e = it2 / tiles, k0 = (it2 - e*tiles) << 5;
        const __half* Bh = Bw + (size_t)e * bstride;
        #pragma unroll
        for (int i = 0; i < 2; i++) {
            uint32_t d = (uint32_t)(brow[i] * LDS + bcol[i]) * 2;
            cp16(smb + OFF_BHI(s) + d, &Bh[(size_t)(n0 + brow[i]) * K + k0 + bcol[i]]);
        }
        cp_commit();
    };
    auto load_a_regs = [&](int it2) {
        int e = it2 / tiles, k0 = (it2 - e*tiles) << 5;
        #pragma unroll
        for (int i = 0; i < 4; i++) {
            ar[i] = *(const float4*)&A[(size_t)(m0 + arow[i]) * K + k0 + acol[i]];
            gv[i] = gate ? gate[(size_t)(m0 + arow[i]) * 4 + e] : 1.f;
        }
    };
    auto store_a = [&](int s) {
        #pragma unroll
        for (int i = 0; i < 4; i++) {
            float4 v = ar[i];
            if (gate) { v.x *= gv[i]; v.y *= gv[i]; v.z *= gv[i]; v.w *= gv[i]; }
            __half hx = __float2half_rn(v.x), hy = __float2half_rn(v.y);
            __half hz = __float2half_rn(v.z), hw = __float2half_rn(v.w);
            __half lx = __float2half_rn(v.x - __half2float(hx));
            __half ly = __float2half_rn(v.y - __half2float(hy));
            __half lz = __float2half_rn(v.z - __half2float(hz));
            __half lw = __float2half_rn(v.w - __half2float(hw));
            int d = arow[i] * LDS + acol[i];
            *(__half2*)(smc + OFF_AHI(s) + d*2)     = __half2(hx, hy);
            *(__half2*)(smc + OFF_AHI(s) + d*2 + 4) = __half2(hz, hw);
            *(__half2*)(smc + OFF_ALO(s) + d*2)     = __half2(lx, ly);
            *(__half2*)(smc + OFF_ALO(s) + d*2 + 4) = __half2(lz, lw);
        }
    };

    // prologue
    load_b(0, 0);
    load_a_regs(0);
    store_a(0);
    cp_wait0();
    __syncthreads();

    for (int it = 0; it < T; it++) {
        int s = it & 1, ns = s ^ 1;
        if (it + 1 < T) {
            load_b(ns, it + 1);
            load_a_regs(it + 1);
        }

        uint32_t aH = smb + OFF_AHI(s), aL = smb + OFF_ALO(s);
        uint32_t bH = smb + OFF_BHI(s);
        #pragma unroll
        for (int ks = 0; ks < 2; ks++) {
            uint32_t bh[4][2], r4[4];
            #pragma unroll
            for (int np = 0; np < 2; np++) {
                uint32_t off = (uint32_t)((wn*32 + np*16 + (lane & 15)) * LDS
                                          + ks*16 + (lane >> 4)*8) * 2;
                ldm_x4(r4, bH + off);
                bh[np*2+0][0] = r4[0]; bh[np*2+0][1] = r4[2];
                bh[np*2+1][0] = r4[1]; bh[np*2+1][1] = r4[3];
            }
            uint32_t ah[4][4], al[4][4];
            #pragma unroll
            for (int mi = 0; mi < 4; mi++) {
                uint32_t off = (uint32_t)((wm*64 + mi*16 + (lane & 15)) * LDS
                                          + ks*16 + (lane >> 4)*8) * 2;
                ldm_x4(ah[mi], aH + off);
                ldm_x4(al[mi], aL + off);
            }
            #pragma unroll
            for (int mi = 0; mi < 4; mi++)
                #pragma unroll
                for (int ni = 0; ni < 4; ni++) {
                    mma16816(acc[mi][ni], ah[mi], bh[ni]);
                    mma16816(acc[mi][ni], al[mi], bh[ni]);
                }
        }
        if (it + 1 < T) {
            store_a(ns);
            cp_wait0();
        }
        __syncthreads();
    }

    // epilogue (fp32 C, gated bias)
    #pragma unroll
    for (int mi = 0; mi < 4; mi++) {
        #pragma unroll
        for (int sub = 0; sub < 2; sub++) {
            int row = m0 + wm*64 + mi*16 + (lane >> 2) + sub*8;
            float4 g4 = make_float4(0.f, 0.f, 0.f, 0.f);
            if (gate) g4 = *(const float4*)&gate[(size_t)row * 4];
            #pragma unroll
            for (int ni = 0; ni < 4; ni++) {
                int cl = wn*32 + ni*8 + (lane & 3)*2;
                float be0, be1;
                if (gate) {
                    be0 = g4.x*sbias[cl]     + g4.y*sbias[128+cl]
                        + g4.z*sbias[256+cl] + g4.w*sbias[384+cl];
                    be1 = g4.x*sbias[cl+1]     + g4.y*sbias[128+cl+1]
                        + g4.z*sbias[256+cl+1] + g4.w*sbias[384+cl+1];
                } else { be0 = sbias[cl]; be1 = sbias[cl+1]; }
                float v0 = acc[mi][ni][sub*2+0] + be0;
                float v1 = acc[mi][ni][sub*2+1] + be1;
                if (relu) { v0 = fmaxf(v0, 0.f); v1 = fmaxf(v1, 0.f); }
                *(float2*)&C[(size_t)row * ldc + coff + n0 + cl] = make_float2(v0, v1);
            }
        }
    }
}

// ---------------- enc3 ----------------
__global__ __launch_bounds__(256) void enc3_kernel(
    const float* __restrict__ cx, const float* __restrict__ cy,
    const float* __restrict__ Wp, const float* __restrict__ bp,
    const float* __restrict__ Wl, const float* __restrict__ bl)
{
    __shared__ float red[256*9];
    __shared__ float h0[HID];
    int b = blockIdx.x, tid = threadIdx.x;
    float l[9];
    #pragma unroll
    for (int x = 0; x < 9; x++) l[x] = 0.f;
    for (int c = tid; c < NC; c += 256) {
        #pragma unroll
        for (int x = 0; x < XD; x++) l[x] += cx[((size_t)b*NC + c)*XD + x];
        l[8] += cy[b*NC + c];
    }
    #pragma unroll
    for (int x = 0; x < 9; x++) red[tid*9 + x] = l[x];
    __syncthreads();
    for (int s = 128; s; s >>= 1) {
        if (tid < s) {
            #pragma unroll
            for (int x = 0; x < 9; x++) red[tid*9 + x] += red[(tid+s)*9 + x];
        }
        __syncthreads();
    }
    {
        int h = tid;
        float a = bp[h];
        #pragma unroll
        for (int x = 0; x < 9; x++) a = fmaf(red[x]*(1.f/NC), Wp[x*HID + h], a);
        h0[h] = a;
    }
    __syncthreads();
    {
        int h = tid;
        float a = bl[h];
        for (int k = 0; k < HID; k++) a = fmaf(h0[k], Wl[k*HID + h], a);
        g_enc3[b*HID + h] = a;
    }
}

// ---------------- per-target encoder ----------------
__global__ __launch_bounds__(256) void target_kernel(
    const float* __restrict__ cx, const float* __restrict__ cy,
    const float* __restrict__ txg,
    const float* __restrict__ Wee, const float* __restrict__ bee,
    const float* __restrict__ Wge, const float* __restrict__ bge,
    const float* __restrict__ Wat, const float* __restrict__ bat)
{
    extern __shared__ float smf[];
    float* sc  = smf;
    float* sWe = sc  + NC*9;
    float* sbe = sWe + NE*9*HID;
    float* sWa = sbe + NE*HID;
    float* sba = sWa + XD*HH;
    float* sWg = sba + HH;
    float* sbg = sWg + XD*NE;

    int b  = blockIdx.x >> 4;
    int t0 = (blockIdx.x & 15) << 7;
    int tid = threadIdx.x;

    for (int i = tid; i < NC*XD; i += 256) sc[(i>>3)*9 + (i&7)] = cx[(size_t)b*NC*XD + i];
    for (int i = tid; i < NC;    i += 256) sc[i*9 + 8] = cy[b*NC + i];
    for (int i = tid; i < NE*9*HID; i += 256) sWe[i] = Wee[i];
    for (int i = tid; i < NE*HID;   i += 256) sbe[i] = bee[i];
    for (int i = tid; i < XD*HH;    i += 256) sWa[i] = Wat[i];
    if (tid < HH)    sba[tid] = bat[tid];
    if (tid < XD*NE) sWg[tid] = Wge[tid];
    if (tid < NE)    sbg[tid] = bge[tid];
    __syncthreads();

    int warp = tid >> 5, lane = tid & 31;
    for (int tt = warp; tt < 128; tt += 8) {
        int t = t0 + tt;
        size_t gt = (size_t)b*NT + t;
        float tx[XD];
        #pragma unroll
        for (int x = 0; x < XD; x++) tx[x] = txg[gt*XD + x];

        float acc[10];
        #pragma unroll
        for (int i = 0; i < 10; i++) acc[i] = 0.f;
        for (int c = lane; c < NC; c += 32) {
            const float* p = &sc[c*9];
            float d2 = 1e-12f;
            #pragma unroll
            for (int x = 0; x < XD; x++) { float d = tx[x]-p[x]; d2 = fmaf(d, d, d2); }
            float dist = d2 * __frsqrt_rn(d2);
            float w = __expf(-dist);
            acc[9] += w;
            #pragma unroll
            for (int x = 0; x < 9; x++) acc[x] = fmaf(w, p[x], acc[x]);
        }
        #pragma unroll
        for (int o = 16; o; o >>= 1) {
            #pragma unroll
            for (int i = 0; i < 10; i++) acc[i] += __shfl_xor_sync(0xffffffffu, acc[i], o);
        }
        float inv = 1.f/acc[9];
        float s[9];
        #pragma unroll
        for (int x = 0; x < 9; x++) s[x] = acc[x]*inv;

        float g[NE];
        #pragma unroll
        for (int e = 0; e < NE; e++) {
            float a = sbg[e];
            #pragma unroll
            for (int x = 0; x < XD; x++) a = fmaf(tx[x], sWg[x*NE + e], a);
            g[e] = a;
        }
        float gm = fmaxf(fmaxf(g[0],g[1]), fmaxf(g[2],g[3]));
        float gs = 0.f;
        #pragma unroll
        for (int e = 0; e < NE; e++) { g[e] = __expf(g[e]-gm); gs += g[e]; }
        float gi = 1.f/gs;
        #pragma unroll
        for (int e = 0; e < NE; e++) g[e] *= gi;

        #pragma unroll
        for (int j = 0; j < 8; j++) {
            int h = lane + 32*j;
            float o2 = 0.f;
            #pragma unroll
            for (int e = 0; e < NE; e++) {
                float a = sbe[e*HID + h];
                #pragma unroll
                for (int x = 0; x < 9; x++) a = fmaf(s[x], sWe[(e*9 + x)*HID + h], a);
                o2 = fmaf(g[e], a, o2);
            }
            g_z[gt*512 + 256 + h] = o2;
            g_z[gt*512 + h] = g_enc3[b*HID + h];
        }
        #pragma unroll
        for (int j = 0; j < 4; j++) {
            int h = lane + 32*j;
            float a = sba[h];
            #pragma unroll
            for (int x = 0; x < XD; x++) a = fmaf(tx[x], sWa[x*HH + h], a);
            g_zd[gt*DD + h] = a;
        }
    }
}

// ---------------- decoder gate ----------------
__global__ __launch_bounds__(256) void decgate_kernel(
    const float* __restrict__ Wg, const float* __restrict__ bg)
{
    int warp = threadIdx.x >> 5, lane = threadIdx.x & 31;
    size_t gt = (size_t)blockIdx.x*8 + warp;
    float a0=0.f, a1=0.f, a2=0.f, a3=0.f;
    const float4* W4 = (const float4*)Wg;
    for (int k = lane; k < DD; k += 32) {
        float z = g_zd[gt*DD + k];
        float4 w = W4[k];
        a0 = fmaf(z, w.x, a0); a1 = fmaf(z, w.y, a1);
        a2 = fmaf(z, w.z, a2); a3 = fmaf(z, w.w, a3);
    }
    #pragma unroll
    for (int o = 16; o; o >>= 1) {
        a0 += __shfl_xor_sync(0xffffffffu, a0, o);
        a1 += __shfl_xor_sync(0xffffffffu, a1, o);
        a2 += __shfl_xor_sync(0xffffffffu, a2, o);
        a3 += __shfl_xor_sync(0xffffffffu, a3, o);
    }
    a0 += bg[0]; a1 += bg[1]; a2 += bg[2]; a3 += bg[3];
    float m = fmaxf(fmaxf(a0,a1), fmaxf(a2,a3));
    float e0 = __expf(a0-m), e1 = __expf(a1-m), e2 = __expf(a2-m), e3 = __expf(a3-m);
    float inv = 1.f/(e0+e1+e2+e3);
    if (lane == 0) {
        g_gd[gt*4+0] = e0*inv; g_gd[gt*4+1] = e1*inv;
        g_gd[gt*4+2] = e2*inv; g_gd[gt*4+3] = e3*inv;
    }
}

// ---------------- head ----------------
__global__ __launch_bounds__(256) void head_kernel(
    const float* __restrict__ W3, const float* __restrict__ b3, float* __restrict__ out)
{
    int warp = threadIdx.x >> 5, lane = threadIdx.x & 31;
    size_t gt = (size_t)blockIdx.x*8 + warp;
    float a0=0.f, a1=0.f;
    const float2* W2 = (const float2*)W3;
    for (int k = lane; k < HID; k += 32) {
        float h = g_h2[gt*HID + k];
        float2 w = W2[k];
        a0 = fmaf(h, w.x, a0); a1 = fmaf(h, w.y, a1);
    }
    #pragma unroll
    for (int o = 16; o; o >>= 1) {
        a0 += __shfl_xor_sync(0xffffffffu, a0, o);
        a1 += __shfl_xor_sync(0xffffffffu, a1, o);
    }
    if (lane == 0) {
        float mu = a0 + b3[0];
        float x  = a1 + b3[1];
        float sp = fmaxf(x, 0.f) + log1pf(__expf(-fabsf(x)));
        out[gt]       = mu;
        out[NTT + gt] = 0.1f + 0.9f*sp;
    }
}

// ---------------- Moran k-NN lag ----------------
__global__ __launch_bounds__(256) void moran_kernel(
    const float* __restrict__ txg, const float* __restrict__ tyg, float* __restrict__ out)
{
    extern __shared__ float smf[];
    float* st  = smf;
    float* sy  = st + NT*9;
    float* smu = sy + NT;
    int b  = blockIdx.x >> 4;
    int t0 = (blockIdx.x & 15) << 7;
    int tid = threadIdx.x;

    for (int i = tid; i < NT*XD; i += 256) st[(i>>3)*9 + (i&7)] = txg[(size_t)b*NT*XD + i];
    for (int i = tid; i < NT; i += 256) { sy[i] = tyg[b*NT + i]; smu[i] = out[b*NT + i]; }
    __syncthreads();
    for (int i = tid; i < NT; i += 256) {
        float n = 0.f;
        #pragma unroll
        for (int x = 0; x < XD; x++) { float v = st[i*9 + x]; n = fmaf(v, v, n); }
        st[i*9 + 8] = n;
    }
    __syncthreads();

    int warp = tid >> 5, lane = tid & 31;
    for (int tt = warp; tt < 128; tt += 8) {
        int t = t0 + tt;
        float tx[XD];
        #pragma unroll
        for (int x = 0; x < XD; x++) tx[x] = st[t*9 + x];
        float tn = st[t*9 + 8];

        float bd0=INFINITY,bd1=INFINITY,bd2=INFINITY,bd3=INFINITY,bd4=INFINITY;
        int   bi0=0,bi1=0,bi2=0,bi3=0,bi4=0;
        for (int c = lane; c < NT; c += 32) {
            if (c == t) continue;
            const float* p = &st[c*9];
            float dot = 0.f;
            #pragma unroll
            for (int x = 0; x < XD; x++) dot = fmaf(tx[x], p[x], dot);
            float d2 = tn + p[8] - 2.f*dot;
            d2 = fmaxf(d2, 0.f) + 1e-12f;
            if (d2 < bd4) {
                bd4 = d2; bi4 = c;
                if (bd4 < bd3) { float td=bd3; bd3=bd4; bd4=td; int ti=bi3; bi3=bi4; bi4=ti; }
                if (bd3 < bd2) { float td=bd2; bd2=bd3; bd3=td; int ti=bi2; bi2=bi3; bi3=ti; }
                if (bd2 < bd1) { float td=bd1; bd1=bd2; bd2=td; int ti=bi1; bi1=bi2; bi2=ti; }
                if (bd1 < bd0) { float td=bd0; bd0=bd1; bd1=td; int ti=bi0; bi0=bi1; bi1=ti; }
            }
        }
        float seld[5]; int seli[5];
        #pragma unroll
        for (int r = 0; r < 5; r++) {
            float rd = bd0; int ri = bi0; int rl = lane;
            #pragma unroll
            for (int o = 16; o; o >>= 1) {
                float od = __shfl_xor_sync(0xffffffffu, rd, o);
                int   oi = __shfl_xor_sync(0xffffffffu, ri, o);
                int   ol = __shfl_xor_sync(0xffffffffu, rl, o);
                if (od < rd || (od == rd && oi < ri)) { rd = od; ri = oi; rl = ol; }
            }
            seld[r] = rd; seli[r] = ri;
            if (lane == rl) {
                bd0=bd1; bi0=bi1; bd1=bd2; bi1=bi2; bd2=bd3; bi2=bi3;
                bd3=bd4; bi3=bi4; bd4=INFINITY; bi4=0x7fffffff;
            }
        }
        if (lane == 0) {
            float w[5], ws = 0.f;
            #pragma unroll
            for (int r = 0; r < 5; r++) { w[r] = __expf(-0.1f*sqrtf(seld[r])); ws += w[r]; }
            float inv = 1.f/ws;
            float ly = 0.f, lm = 0.f;
            #pragma unroll
            for (int r = 0; r < 5; r++) {
                float wr = w[r]*inv;
                ly = fmaf(wr, sy[seli[r]],  ly);
                lm = fmaf(wr, smu[seli[r]], lm);
            }
            size_t gt = (size_t)b*NT + t;
            out[2*(size_t)NTT + gt] = ly;
            out[3*(size_t)NTT + gt] = lm;
        }
    }
}

// ---------------- launch ----------------
extern "C" void kernel_launch(void* const* d_in, const int* in_sizes, int n_in,
                              void* d_out, int out_size)
{
    const float* cx   = (const float*)d_in[0];
    const float* cy   = (const float*)d_in[1];
    const float* txp  = (const float*)d_in[2];
    const float* typ  = (const float*)d_in[3];
    const float* Wge  = (const float*)d_in[4];
    const float* bge  = (const float*)d_in[5];
    const float* Wee  = (const float*)d_in[6];
    const float* bee  = (const float*)d_in[7];
    const float* Wp3  = (const float*)d_in[8];
    const float* bp3  = (const float*)d_in[9];
    const float* Wlin = (const float*)d_in[10];
    const float* blin = (const float*)d_in[11];
    const float* Wf1  = (const float*)d_in[12];
    const float* bf1  = (const float*)d_in[13];
    const float* Wf2  = (const float*)d_in[14];
    const float* bf2  = (const float*)d_in[15];
    const float* Wat  = (const float*)d_in[16];
    const float* bat  = (const float*)d_in[17];
    const float* Wgd  = (const float*)d_in[18];
    const float* bgd  = (const float*)d_in[19];
    const float* Wed  = (const float*)d_in[20];
    const float* bed  = (const float*)d_in[21];
    const float* Wd1  = (const float*)d_in[22];
    const float* bd1  = (const float*)d_in[23];
    const float* Wd2  = (const float*)d_in[24];
    const float* bd2  = (const float*)d_in[25];
    const float* Wd3  = (const float*)d_in[26];
    const float* bd3  = (const float*)d_in[27];
    float* out = (float*)d_out;

    float *p_z, *p_fh, *p_zd, *p_zd2, *p_h1, *p_h2, *p_gd;
    cudaGetSymbolAddress((void**)&p_z,   g_z);
    cudaGetSymbolAddress((void**)&p_fh,  g_fh);
    cudaGetSymbolAddress((void**)&p_zd,  g_zd);
    cudaGetSymbolAddress((void**)&p_zd2, g_zd2);
    cudaGetSymbolAddress((void**)&p_h1,  g_h1);
    cudaGetSymbolAddress((void**)&p_h2,  g_h2);
    cudaGetSymbolAddress((void**)&p_gd,  g_gd);
    __half *wf1, *wf2, *wm, *wd1, *wd2;
    cudaGetSymbolAddress((void**)&wf1, g_wf1);
    cudaGetSymbolAddress((void**)&wf2, g_wf2);
    cudaGetSymbolAddress((void**)&wm,  g_wm);
    cudaGetSymbolAddress((void**)&wd1, g_wd1);
    cudaGetSymbolAddress((void**)&wd2, g_wd2);

    const int smem_t = (NC*9 + NE*9*HID + NE*HID + XD*HH + HH + XD*NE + NE)*4;
    const int smem_m = (NT*9 + NT + NT)*4;
    cudaFuncSetAttribute(target_kernel, cudaFuncAttributeMaxDynamicSharedMemorySize, smem_t);
    cudaFuncSetAttribute(moran_kernel,  cudaFuncAttributeMaxDynamicSharedMemorySize, smem_m);
    cudaFuncSetAttribute(mma_gemm,      cudaFuncAttributeMaxDynamicSharedMemorySize, SMEM_GEMM);

    prep_w<<<dim3(256,1), 256>>>(Wf1, wf1, 512, 128);
    prep_w<<<dim3(128,1), 256>>>(Wf2, wf2, 128, 256);
    prep_w<<<dim3(576,4), 256>>>(Wed, wm,  384, 384);
    prep_w<<<dim3(384,1), 256>>>(Wd1, wd1, 384, 256);
    prep_w<<<dim3(256,1), 256>>>(Wd2, wd2, 256, 256);

    enc3_kernel<<<BSZ, 256>>>(cx, cy, Wp3, bp3, Wlin, blin);
    target_kernel<<<256, 256, smem_t>>>(cx, cy, txp, Wee, bee, Wge, bge, Wat, bat);
    // fps1: relu(z @ Wf1 + b)
    mma_gemm<<<dim3(256,1), 256, SMEM_GEMM>>>(p_z,   wf1, bf1, nullptr, p_fh,  512, 128, 0,   1, 1);
    // fps2: r = fh @ Wf2 + b -> zd[:,128:384]
    mma_gemm<<<dim3(256,2), 256, SMEM_GEMM>>>(p_fh,  wf2, bf2, nullptr, p_zd,  128, 384, 128, 1, 0);
    decgate_kernel<<<NTT/8, 256>>>(Wgd, bgd);
    // decoder MoE (gate-scaled A rows, accumulate over experts)
    mma_gemm<<<dim3(256,3), 256, SMEM_GEMM>>>(p_zd,  wm,  bed, p_gd,    p_zd2, 384, 384, 0,   4, 0);
    mma_gemm<<<dim3(256,2), 256, SMEM_GEMM>>>(p_zd2, wd1, bd1, nullptr, p_h1,  384, 256, 0,   1, 1);
    mma_gemm<<<dim3(256,2), 256, SMEM_GEMM>>>(p_h1,  wd2, bd2, nullptr, p_h2,  256, 256, 0,   1, 1);
    head_kernel<<<NTT/8, 256>>>(Wd3, bd3, out);
    moran_kernel<<<256, 256, smem_m>>>(txp, typ, out);
}

// round 8
// speedup vs baseline: 1.7220x; 1.2824x over previous
#include <cuda_runtime.h>
#include <cuda_fp16.h>
#include <cstdint>
#include <math.h>

#define BSZ 16
#define NC  1024
#define NT  2048
#define NTT (BSZ*NT)
#define XD  8
#define HID 256
#define HH  128
#define DD  384
#define NE  4

// ---------------- scratch ----------------
__device__ float g_enc3[BSZ*HID];
__device__ float g_gd [(size_t)NTT*NE];

// activations: single fp16
__device__ __half g_z  [(size_t)NTT*512];
__device__ __half g_fh [(size_t)NTT*HH];
__device__ __half g_zd [(size_t)NTT*DD];
__device__ __half g_zd2[(size_t)NTT*DD];
__device__ __half g_h1 [(size_t)NTT*HID];
__device__ __half g_h2 [(size_t)NTT*HID];

// weights: single fp16, pre-transposed to [N,K] K-major
__device__ __half g_wf1[128*512];
__device__ __half g_wf2[256*128];
__device__ __half g_wm [4*384*384];
__device__ __half g_wd1[256*384];
__device__ __half g_wd2[256*256];

// ---------------- weight prep: transpose + fp16 round ----------------
__global__ __launch_bounds__(256) void prep_w(
    const float* __restrict__ W, __half* __restrict__ hi, int K, int N)
{
    int e = blockIdx.y;
    size_t base = (size_t)e*K*N;
    for (int idx = blockIdx.x*256 + threadIdx.x; idx < K*N; idx += gridDim.x*256) {
        int n = idx / K, k = idx - n*K;
        hi[base + idx] = __float2half_rn(W[base + (size_t)k*N + n]);
    }
}

// ---------------- mma.sync helpers ----------------
__device__ __forceinline__ uint32_t smem_u32(const void* p) {
    uint32_t a;
    asm("{ .reg .u64 t; cvta.to.shared.u64 t, %1; cvt.u32.u64 %0, t; }" : "=r"(a) : "l"(p));
    return a;
}
__device__ __forceinline__ void ldm_x4(uint32_t* r, uint32_t addr) {
    asm volatile("ldmatrix.sync.aligned.m8n8.x4.shared.b16 {%0,%1,%2,%3}, [%4];"
        : "=r"(r[0]), "=r"(r[1]), "=r"(r[2]), "=r"(r[3]) : "r"(addr));
}
__device__ __forceinline__ void mma16816(float* d, const uint32_t* a, const uint32_t* b) {
    asm volatile(
        "mma.sync.aligned.m16n8k16.row.col.f32.f16.f16.f32 "
        "{%0,%1,%2,%3}, {%4,%5,%6,%7}, {%8,%9}, {%0,%1,%2,%3};"
        : "+f"(d[0]), "+f"(d[1]), "+f"(d[2]), "+f"(d[3])
        : "r"(a[0]), "r"(a[1]), "r"(a[2]), "r"(a[3]), "r"(b[0]), "r"(b[1]));
}
__device__ __forceinline__ void cp16(uint32_t dst, const void* src) {
    asm volatile("cp.async.ca.shared.global [%0], [%1], 16;" :: "r"(dst), "l"(src));
}
__device__ __forceinline__ void cp_commit() { asm volatile("cp.async.commit_group;"); }
__device__ __forceinline__ void cp_wait0()  { asm volatile("cp.async.wait_group 0;"); }

// smem: fp16, row stride 40 elems (80B), 128x32 tiles
#define LDS   40
#define TILEB 10240
#define OFF_A(s) ((s)*TILEB)
#define OFF_B(s) ((2+(s))*TILEB)
#define SMEM_GEMM  40960

// C[M,Nfull](@ldc,coff) fp16 = act( rowscale(A) @ B^T + bias_eff )
// A fp16, B fp16 [N,K] expert-stacked; gate!=null: A rows scaled per expert
// (LDG+scale+STS path), acc over experts, gated bias. Non-gated: pure cp.async.
__global__ __launch_bounds__(256) void mma_gemm(
    const __half* __restrict__ A, const __half* __restrict__ Bw,
    const float* __restrict__ bias, const float* __restrict__ gate,
    __half* __restrict__ C,
    int K, int ldc, int coff, int nexp, int relu)
{
    extern __shared__ char smc[];
    __shared__ float sbias[NE*128];
    uint32_t smb = smem_u32(smc);
    int tid = threadIdx.x;
    int lane = tid & 31, warp = tid >> 5;
    int wm = warp >> 2, wn = warp & 3;          // 2x4 warps: 64x32 warp tile
    int m0 = blockIdx.x * 128, n0 = blockIdx.y * 128;
    int Nfull = gridDim.y * 128;
    size_t bstride = (size_t)Nfull * K;

    for (int i = tid; i < nexp*128; i += 256)
        sbias[i] = bias[(size_t)(i >> 7) * Nfull + n0 + (i & 127)];

    float acc[4][4][4];
    #pragma unroll
    for (int mi = 0; mi < 4; mi++)
        #pragma unroll
        for (int ni = 0; ni < 4; ni++)
            #pragma unroll
            for (int q = 0; q < 4; q++) acc[mi][ni][q] = 0.f;

    const int tiles = K >> 5;
    const int T = nexp * tiles;

    // 16B chunk mapping (both A and B tiles: 128 rows x 32 fp16 = 512 chunks)
    int crow[2], ccol[2];
    #pragma unroll
    for (int i = 0; i < 2; i++) { int c = tid + i*256; crow[i] = c >> 2; ccol[i] = (c & 3) << 3; }

    uint4 ar[2]; float gv[2];

    auto load_async = [&](int s, int it2) {
        int e = it2 / tiles, k0 = (it2 - e*tiles) << 5;
        const __half* Bh = Bw + (size_t)e * bstride;
        #pragma unroll
        for (int i = 0; i < 2; i++) {
            uint32_t d = (uint32_t)(crow[i] * LDS + ccol[i]) * 2;
            cp16(smb + OFF_B(s) + d, &Bh[(size_t)(n0 + crow[i]) * K + k0 + ccol[i]]);
            if (!gate)
                cp16(smb + OFF_A(s) + d, &A[(size_t)(m0 + crow[i]) * K + k0 + ccol[i]]);
        }
        cp_commit();
    };
    auto load_a_regs = [&](int it2) {
        int e = it2 / tiles, k0 = (it2 - e*tiles) << 5;
        #pragma unroll
        for (int i = 0; i < 2; i++) {
            ar[i] = *(const uint4*)&A[(size_t)(m0 + crow[i]) * K + k0 + ccol[i]];
            gv[i] = gate[(size_t)(m0 + crow[i]) * 4 + e];
        }
    };
    auto store_a = [&](int s) {
        #pragma unroll
        for (int i = 0; i < 2; i++) {
            const uint32_t* pp = (const uint32_t*)&ar[i];
            uint32_t o[4];
            #pragma unroll
            for (int q = 0; q < 4; q++) {
                __half2 h2 = *(const __half2*)&pp[q];
                float2 f = __half22float2(h2);
                o[q] = *(uint32_t*)&(*(__half2*)&h2);
                __half2 r = __floats2half2_rn(f.x * gv[i], f.y * gv[i]);
                o[q] = *(const uint32_t*)&r;
            }
            uint32_t d = (uint32_t)(crow[i] * LDS + ccol[i]) * 2;
            *(uint4*)(smc + OFF_A(s) + d) = make_uint4(o[0], o[1], o[2], o[3]);
        }
    };

    // prologue
    load_async(0, 0);
    if (gate) { load_a_regs(0); store_a(0); }
    cp_wait0();
    __syncthreads();

    for (int it = 0; it < T; it++) {
        int s = it & 1, ns = s ^ 1;
        if (it + 1 < T) {
            load_async(ns, it + 1);
            if (gate) load_a_regs(it + 1);
        }

        uint32_t aS = smb + OFF_A(s), bS = smb + OFF_B(s);
        #pragma unroll
        for (int ks = 0; ks < 2; ks++) {
            uint32_t bh[4][2], r4[4];
            #pragma unroll
            for (int np = 0; np < 2; np++) {
                uint32_t off = (uint32_t)((wn*32 + np*16 + (lane & 15)) * LDS
                                          + ks*16 + (lane >> 4)*8) * 2;
                ldm_x4(r4, bS + off);
                bh[np*2+0][0] = r4[0]; bh[np*2+0][1] = r4[2];
                bh[np*2+1][0] = r4[1]; bh[np*2+1][1] = r4[3];
            }
            uint32_t ah[4][4];
            #pragma unroll
            for (int mi = 0; mi < 4; mi++) {
                uint32_t off = (uint32_t)((wm*64 + mi*16 + (lane & 15)) * LDS
                                          + ks*16 + (lane >> 4)*8) * 2;
                ldm_x4(ah[mi], aS + off);
            }
            #pragma unroll
            for (int mi = 0; mi < 4; mi++)
                #pragma unroll
                for (int ni = 0; ni < 4; ni++)
                    mma16816(acc[mi][ni], ah[mi], bh[ni]);
        }
        if (it + 1 < T) {
            if (gate) store_a(ns);
            cp_wait0();
        }
        __syncthreads();
    }

    // epilogue: fp16 C, gated bias
    #pragma unroll
    for (int mi = 0; mi < 4; mi++) {
        #pragma unroll
        for (int sub = 0; sub < 2; sub++) {
            int row = m0 + wm*64 + mi*16 + (lane >> 2) + sub*8;
            float4 g4 = make_float4(0.f, 0.f, 0.f, 0.f);
            if (gate) g4 = *(const float4*)&gate[(size_t)row * 4];
            #pragma unroll
            for (int ni = 0; ni < 4; ni++) {
                int cl = wn*32 + ni*8 + (lane & 3)*2;
                float be0, be1;
                if (gate) {
                    be0 = g4.x*sbias[cl]     + g4.y*sbias[128+cl]
                        + g4.z*sbias[256+cl] + g4.w*sbias[384+cl];
                    be1 = g4.x*sbias[cl+1]     + g4.y*sbias[128+cl+1]
                        + g4.z*sbias[256+cl+1] + g4.w*sbias[384+cl+1];
                } else { be0 = sbias[cl]; be1 = sbias[cl+1]; }
                float v0 = acc[mi][ni][sub*2+0] + be0;
                float v1 = acc[mi][ni][sub*2+1] + be1;
                if (relu) { v0 = fmaxf(v0, 0.f); v1 = fmaxf(v1, 0.f); }
                *(__half2*)&C[(size_t)row * ldc + coff + n0 + cl] = __floats2half2_rn(v0, v1);
            }
        }
    }
}

// ---------------- enc3 ----------------
__global__ __launch_bounds__(256) void enc3_kernel(
    const float* __restrict__ cx, const float* __restrict__ cy,
    const float* __restrict__ Wp, const float* __restrict__ bp,
    const float* __restrict__ Wl, const float* __restrict__ bl)
{
    __shared__ float red[256*9];
    __shared__ float h0[HID];
    int b = blockIdx.x, tid = threadIdx.x;
    float l[9];
    #pragma unroll
    for (int x = 0; x < 9; x++) l[x] = 0.f;
    for (int c = tid; c < NC; c += 256) {
        #pragma unroll
        for (int x = 0; x < XD; x++) l[x] += cx[((size_t)b*NC + c)*XD + x];
        l[8] += cy[b*NC + c];
    }
    #pragma unroll
    for (int x = 0; x < 9; x++) red[tid*9 + x] = l[x];
    __syncthreads();
    for (int s = 128; s; s >>= 1) {
        if (tid < s) {
            #pragma unroll
            for (int x = 0; x < 9; x++) red[tid*9 + x] += red[(tid+s)*9 + x];
        }
        __syncthreads();
    }
    {
        int h = tid;
        float a = bp[h];
        #pragma unroll
        for (int x = 0; x < 9; x++) a = fmaf(red[x]*(1.f/NC), Wp[x*HID + h], a);
        h0[h] = a;
    }
    __syncthreads();
    {
        int h = tid;
        float a = bl[h];
        for (int k = 0; k < HID; k++) a = fmaf(h0[k], Wl[k*HID + h], a);
        g_enc3[b*HID + h] = a;
    }
}

// ---------------- per-target encoder (writes fp16 activations) ----------------
__global__ __launch_bounds__(256) void target_kernel(
    const float* __restrict__ cx, const float* __restrict__ cy,
    const float* __restrict__ txg,
    const float* __restrict__ Wee, const float* __restrict__ bee,
    const float* __restrict__ Wge, const float* __restrict__ bge,
    const float* __restrict__ Wat, const float* __restrict__ bat)
{
    extern __shared__ float smf[];
    float* sc  = smf;
    float* sWe = sc  + NC*9;
    float* sbe = sWe + NE*9*HID;
    float* sWa = sbe + NE*HID;
    float* sba = sWa + XD*HH;
    float* sWg = sba + HH;
    float* sbg = sWg + XD*NE;

    int b  = blockIdx.x >> 4;
    int t0 = (blockIdx.x & 15) << 7;
    int tid = threadIdx.x;

    for (int i = tid; i < NC*XD; i += 256) sc[(i>>3)*9 + (i&7)] = cx[(size_t)b*NC*XD + i];
    for (int i = tid; i < NC;    i += 256) sc[i*9 + 8] = cy[b*NC + i];
    for (int i = tid; i < NE*9*HID; i += 256) sWe[i] = Wee[i];
    for (int i = tid; i < NE*HID;   i += 256) sbe[i] = bee[i];
    for (int i = tid; i < XD*HH;    i += 256) sWa[i] = Wat[i];
    if (tid < HH)    sba[tid] = bat[tid];
    if (tid < XD*NE) sWg[tid] = Wge[tid];
    if (tid < NE)    sbg[tid] = bge[tid];
    __syncthreads();

    int warp = tid >> 5, lane = tid & 31;
    for (int tt = warp; tt < 128; tt += 8) {
        int t = t0 + tt;
        size_t gt = (size_t)b*NT + t;
        float tx[XD];
        #pragma unroll
        for (int x = 0; x < XD; x++) tx[x] = txg[gt*XD + x];

        float acc[10];
        #pragma unroll
        for (int i = 0; i < 10; i++) acc[i] = 0.f;
        for (int c = lane; c < NC; c += 32) {
            const float* p = &sc[c*9];
            float d2 = 1e-12f;
            #pragma unroll
            for (int x = 0; x < XD; x++) { float d = tx[x]-p[x]; d2 = fmaf(d, d, d2); }
            float dist = d2 * __frsqrt_rn(d2);
            float w = __expf(-dist);
            acc[9] += w;
            #pragma unroll
            for (int x = 0; x < 9; x++) acc[x] = fmaf(w, p[x], acc[x]);
        }
        #pragma unroll
        for (int o = 16; o; o >>= 1) {
            #pragma unroll
            for (int i = 0; i < 10; i++) acc[i] += __shfl_xor_sync(0xffffffffu, acc[i], o);
        }
        float inv = 1.f/acc[9];
        float s[9];
        #pragma unroll
        for (int x = 0; x < 9; x++) s[x] = acc[x]*inv;

        float g[NE];
        #pragma unroll
        for (int e = 0; e < NE; e++) {
            float a = sbg[e];
            #pragma unroll
            for (int x = 0; x < XD; x++) a = fmaf(tx[x], sWg[x*NE + e], a);
            g[e] = a;
        }
        float gm = fmaxf(fmaxf(g[0],g[1]), fmaxf(g[2],g[3]));
        float gs = 0.f;
        #pragma unroll
        for (int e = 0; e < NE; e++) { g[e] = __expf(g[e]-gm); gs += g[e]; }
        float gi = 1.f/gs;
        #pragma unroll
        for (int e = 0; e < NE; e++) g[e] *= gi;

        #pragma unroll
        for (int j = 0; j < 8; j++) {
            int h = lane + 32*j;
            float o2 = 0.f;
            #pragma unroll
            for (int e = 0; e < NE; e++) {
                float a = sbe[e*HID + h];
                #pragma unroll
                for (int x = 0; x < 9; x++) a = fmaf(s[x], sWe[(e*9 + x)*HID + h], a);
                o2 = fmaf(g[e], a, o2);
            }
            g_z[gt*512 + 256 + h] = __float2half_rn(o2);
            g_z[gt*512 + h] = __float2half_rn(g_enc3[b*HID + h]);
        }
        #pragma unroll
        for (int j = 0; j < 4; j++) {
            int h = lane + 32*j;
            float a = sba[h];
            #pragma unroll
            for (int x = 0; x < XD; x++) a = fmaf(tx[x], sWa[x*HH + h], a);
            g_zd[gt*DD + h] = __float2half_rn(a);
        }
    }
}

// ---------------- decoder gate ----------------
__global__ __launch_bounds__(256) void decgate_kernel(
    const float* __restrict__ Wg, const float* __restrict__ bg)
{
    int warp = threadIdx.x >> 5, lane = threadIdx.x & 31;
    size_t gt = (size_t)blockIdx.x*8 + warp;
    float a0=0.f, a1=0.f, a2=0.f, a3=0.f;
    const float4* W4 = (const float4*)Wg;
    for (int k = lane; k < DD; k += 32) {
        float z = __half2float(g_zd[gt*DD + k]);
        float4 w = W4[k];
        a0 = fmaf(z, w.x, a0); a1 = fmaf(z, w.y, a1);
        a2 = fmaf(z, w.z, a2); a3 = fmaf(z, w.w, a3);
    }
    #pragma unroll
    for (int o = 16; o; o >>= 1) {
        a0 += __shfl_xor_sync(0xffffffffu, a0, o);
        a1 += __shfl_xor_sync(0xffffffffu, a1, o);
        a2 += __shfl_xor_sync(0xffffffffu, a2, o);
        a3 += __shfl_xor_sync(0xffffffffu, a3, o);
    }
    a0 += bg[0]; a1 += bg[1]; a2 += bg[2]; a3 += bg[3];
    float m = fmaxf(fmaxf(a0,a1), fmaxf(a2,a3));
    float e0 = __expf(a0-m), e1 = __expf(a1-m), e2 = __expf(a2-m), e3 = __expf(a3-m);
    float inv = 1.f/(e0+e1+e2+e3);
    if (lane == 0) {
        g_gd[gt*4+0] = e0*inv; g_gd[gt*4+1] = e1*inv;
        g_gd[gt*4+2] = e2*inv; g_gd[gt*4+3] = e3*inv;
    }
}

// ---------------- head ----------------
__global__ __launch_bounds__(256) void head_kernel(
    const float* __restrict__ W3, const float* __restrict__ b3, float* __restrict__ out)
{
    int warp = threadIdx.x >> 5, lane = threadIdx.x & 31;
    size_t gt = (size_t)blockIdx.x*8 + warp;
    float a0=0.f, a1=0.f;
    const float2* W2 = (const float2*)W3;
    for (int k = lane; k < HID; k += 32) {
        float h = __half2float(g_h2[gt*HID + k]);
        float2 w = W2[k];
        a0 = fmaf(h, w.x, a0); a1 = fmaf(h, w.y, a1);
    }
    #pragma unroll
    for (int o = 16; o; o >>= 1) {
        a0 += __shfl_xor_sync(0xffffffffu, a0, o);
        a1 += __shfl_xor_sync(0xffffffffu, a1, o);
    }
    if (lane == 0) {
        float mu = a0 + b3[0];
        float x  = a1 + b3[1];
        float sp = fmaxf(x, 0.f) + log1pf(__expf(-fabsf(x)));
        out[gt]       = mu;
        out[NTT + gt] = 0.1f + 0.9f*sp;
    }
}

// ---------------- Moran k-NN lag ----------------
__global__ __launch_bounds__(256) void moran_kernel(
    const float* __restrict__ txg, const float* __restrict__ tyg, float* __restrict__ out)
{
    extern __shared__ float smf[];
    float* st  = smf;
    float* sy  = st + NT*9;
    float* smu = sy + NT;
    int b  = blockIdx.x >> 4;
    int t0 = (blockIdx.x & 15) << 7;
    int tid = threadIdx.x;

    for (int i = tid; i < NT*XD; i += 256) st[(i>>3)*9 + (i&7)] = txg[(size_t)b*NT*XD + i];
    for (int i = tid; i < NT; i += 256) { sy[i] = tyg[b*NT + i]; smu[i] = out[b*NT + i]; }
    __syncthreads();
    for (int i = tid; i < NT; i += 256) {
        float n = 0.f;
        #pragma unroll
        for (int x = 0; x < XD; x++) { float v = st[i*9 + x]; n = fmaf(v, v, n); }
        st[i*9 + 8] = n;
    }
    __syncthreads();

    int warp = tid >> 5, lane = tid & 31;
    for (int tt = warp; tt < 128; tt += 8) {
        int t = t0 + tt;
        float tx[XD];
        #pragma unroll
        for (int x = 0; x < XD; x++) tx[x] = st[t*9 + x];
        float tn = st[t*9 + 8];

        float bd0=INFINITY,bd1=INFINITY,bd2=INFINITY,bd3=INFINITY,bd4=INFINITY;
        int   bi0=0,bi1=0,bi2=0,bi3=0,bi4=0;
        for (int c = lane; c < NT; c += 32) {
            if (c == t) continue;
            const float* p = &st[c*9];
            float dot = 0.f;
            #pragma unroll
            for (int x = 0; x < XD; x++) dot = fmaf(tx[x], p[x], dot);
            float d2 = tn + p[8] - 2.f*dot;
            d2 = fmaxf(d2, 0.f) + 1e-12f;
            if (d2 < bd4) {
                bd4 = d2; bi4 = c;
                if (bd4 < bd3) { float td=bd3; bd3=bd4; bd4=td; int ti=bi3; bi3=bi4; bi4=ti; }
                if (bd3 < bd2) { float td=bd2; bd2=bd3; bd3=td; int ti=bi2; bi2=bi3; bi3=ti; }
                if (bd2 < bd1) { float td=bd1; bd1=bd2; bd2=td; int ti=bi1; bi1=bi2; bi2=ti; }
                if (bd1 < bd0) { float td=bd0; bd0=bd1; bd1=td; int ti=bi0; bi0=bi1; bi1=ti; }
            }
        }
        float seld[5]; int seli[5];
        #pragma unroll
        for (int r = 0; r < 5; r++) {
            float rd = bd0; int ri = bi0; int rl = lane;
            #pragma unroll
            for (int o = 16; o; o >>= 1) {
                float od = __shfl_xor_sync(0xffffffffu, rd, o);
                int   oi = __shfl_xor_sync(0xffffffffu, ri, o);
                int   ol = __shfl_xor_sync(0xffffffffu, rl, o);
                if (od < rd || (od == rd && oi < ri)) { rd = od; ri = oi; rl = ol; }
            }
            seld[r] = rd; seli[r] = ri;
            if (lane == rl) {
                bd0=bd1; bi0=bi1; bd1=bd2; bi1=bi2; bd2=bd3; bi2=bi3;
                bd3=bd4; bi3=bi4; bd4=INFINITY; bi4=0x7fffffff;
            }
        }
        if (lane == 0) {
            float w[5], ws = 0.f;
            #pragma unroll
            for (int r = 0; r < 5; r++) { w[r] = __expf(-0.1f*sqrtf(seld[r])); ws += w[r]; }
            float inv = 1.f/ws;
            float ly = 0.f, lm = 0.f;
            #pragma unroll
            for (int r = 0; r < 5; r++) {
                float wr = w[r]*inv;
                ly = fmaf(wr, sy[seli[r]],  ly);
                lm = fmaf(wr, smu[seli[r]], lm);
            }
            size_t gt = (size_t)b*NT + t;
            out[2*(size_t)NTT + gt] = ly;
            out[3*(size_t)NTT + gt] = lm;
        }
    }
}

// ---------------- launch ----------------
extern "C" void kernel_launch(void* const* d_in, const int* in_sizes, int n_in,
                              void* d_out, int out_size)
{
    const float* cx   = (const float*)d_in[0];
    const float* cy   = (const float*)d_in[1];
    const float* txp  = (const float*)d_in[2];
    const float* typ  = (const float*)d_in[3];
    const float* Wge  = (const float*)d_in[4];
    const float* bge  = (const float*)d_in[5];
    const float* Wee  = (const float*)d_in[6];
    const float* bee  = (const float*)d_in[7];
    const float* Wp3  = (const float*)d_in[8];
    const float* bp3  = (const float*)d_in[9];
    const float* Wlin = (const float*)d_in[10];
    const float* blin = (const float*)d_in[11];
    const float* Wf1  = (const float*)d_in[12];
    const float* bf1  = (const float*)d_in[13];
    const float* Wf2  = (const float*)d_in[14];
    const float* bf2  = (const float*)d_in[15];
    const float* Wat  = (const float*)d_in[16];
    const float* bat  = (const float*)d_in[17];
    const float* Wgd  = (const float*)d_in[18];
    const float* bgd  = (const float*)d_in[19];
    const float* Wed  = (const float*)d_in[20];
    const float* bed  = (const float*)d_in[21];
    const float* Wd1  = (const float*)d_in[22];
    const float* bd1  = (const float*)d_in[23];
    const float* Wd2  = (const float*)d_in[24];
    const float* bd2  = (const float*)d_in[25];
    const float* Wd3  = (const float*)d_in[26];
    const float* bd3  = (const float*)d_in[27];
    float* out = (float*)d_out;

    float *p_gd;
    cudaGetSymbolAddress((void**)&p_gd, g_gd);
    __half *p_z, *p_fh, *p_zd, *p_zd2, *p_h1, *p_h2;
    cudaGetSymbolAddress((void**)&p_z,   g_z);
    cudaGetSymbolAddress((void**)&p_fh,  g_fh);
    cudaGetSymbolAddress((void**)&p_zd,  g_zd);
    cudaGetSymbolAddress((void**)&p_zd2, g_zd2);
    cudaGetSymbolAddress((void**)&p_h1,  g_h1);
    cudaGetSymbolAddress((void**)&p_h2,  g_h2);
    __half *wf1, *wf2, *wm, *wd1, *wd2;
    cudaGetSymbolAddress((void**)&wf1, g_wf1);
    cudaGetSymbolAddress((void**)&wf2, g_wf2);
    cudaGetSymbolAddress((void**)&wm,  g_wm);
    cudaGetSymbolAddress((void**)&wd1, g_wd1);
    cudaGetSymbolAddress((void**)&wd2, g_wd2);

    const int smem_t = (NC*9 + NE*9*HID + NE*HID + XD*HH + HH + XD*NE + NE)*4;
    const int smem_m = (NT*9 + NT + NT)*4;
    cudaFuncSetAttribute(target_kernel, cudaFuncAttributeMaxDynamicSharedMemorySize, smem_t);
    cudaFuncSetAttribute(moran_kernel,  cudaFuncAttributeMaxDynamicSharedMemorySize, smem_m);
    cudaFuncSetAttribute(mma_gemm,      cudaFuncAttributeMaxDynamicSharedMemorySize, SMEM_GEMM);

    prep_w<<<dim3(256,1), 256>>>(Wf1, wf1, 512, 128);
    prep_w<<<dim3(128,1), 256>>>(Wf2, wf2, 128, 256);
    prep_w<<<dim3(576,4), 256>>>(Wed, wm,  384, 384);
    prep_w<<<dim3(384,1), 256>>>(Wd1, wd1, 384, 256);
    prep_w<<<dim3(256,1), 256>>>(Wd2, wd2, 256, 256);

    enc3_kernel<<<BSZ, 256>>>(cx, cy, Wp3, bp3, Wlin, blin);
    target_kernel<<<256, 256, smem_t>>>(cx, cy, txp, Wee, bee, Wge, bge, Wat, bat);
    // fps1: relu(z @ Wf1 + b)
    mma_gemm<<<dim3(256,1), 256, SMEM_GEMM>>>(p_z,   wf1, bf1, nullptr, p_fh,  512, 128, 0,   1, 1);
    // fps2: r = fh @ Wf2 + b -> zd[:,128:384]
    mma_gemm<<<dim3(256,2), 256, SMEM_GEMM>>>(p_fh,  wf2, bf2, nullptr, p_zd,  128, 384, 128, 1, 0);
    decgate_kernel<<<NTT/8, 256>>>(Wgd, bgd);
    // decoder MoE (gate-scaled A rows, accumulate over experts)
    mma_gemm<<<dim3(256,3), 256, SMEM_GEMM>>>(p_zd,  wm,  bed, p_gd,    p_zd2, 384, 384, 0,   4, 0);
    mma_gemm<<<dim3(256,2), 256, SMEM_GEMM>>>(p_zd2, wd1, bd1, nullptr, p_h1,  384, 256, 0,   1, 1);
    mma_gemm<<<dim3(256,2), 256, SMEM_GEMM>>>(p_h1,  wd2, bd2, nullptr, p_h2,  256, 256, 0,   1, 1);
    head_kernel<<<NTT/8, 256>>>(Wd3, bd3, out);
    moran_kernel<<<256, 256, smem_m>>>(txp, typ, out);
}

// round 9
// speedup vs baseline: 1.7761x; 1.0314x over previous
#include <cuda_runtime.h>
#include <cuda_fp16.h>
#include <cstdint>
#include <math.h>

#define BSZ 16
#define NC  1024
#define NT  2048
#define NTT (BSZ*NT)
#define XD  8
#define HID 256
#define HH  128
#define DD  384
#define NE  4

// ---------------- scratch ----------------
__device__ float g_enc3[BSZ*HID];
__device__ float g_gd [(size_t)NTT*NE];

// activations: single fp16
__device__ __half g_z  [(size_t)NTT*512];
__device__ __half g_fh [(size_t)NTT*HH];
__device__ __half g_zd [(size_t)NTT*DD];
__device__ __half g_zd2[(size_t)NTT*DD];
__device__ __half g_h1 [(size_t)NTT*HID];
__device__ __half g_h2 [(size_t)NTT*HID];

// weights: single fp16, pre-transposed to [N,K] K-major
__device__ __half g_wf1[128*512];
__device__ __half g_wf2[256*128];
__device__ __half g_wm [4*384*384];
__device__ __half g_wd1[256*384];
__device__ __half g_wd2[256*256];

// ---------------- weight prep: all 5 tensors in one launch ----------------
struct PrepDesc { const float* W; __half* O; int K; int N; int total; };

__global__ __launch_bounds__(256) void prep_all(
    PrepDesc d0, PrepDesc d1, PrepDesc d2, PrepDesc d3, PrepDesc d4)
{
    PrepDesc d;
    switch (blockIdx.y) {
        case 0: d = d0; break;
        case 1: d = d1; break;
        case 2: d = d2; break;
        case 3: d = d3; break;
        default: d = d4; break;
    }
    int KN = d.K * d.N;
    for (int idx = blockIdx.x*256 + threadIdx.x; idx < d.total; idx += gridDim.x*256) {
        int e = idx / KN, rem = idx - e*KN;
        int n = rem / d.K, k = rem - n*d.K;
        d.O[idx] = __float2half_rn(d.W[(size_t)e*KN + (size_t)k*d.N + n]);
    }
}

// ---------------- mma.sync helpers ----------------
__device__ __forceinline__ uint32_t smem_u32(const void* p) {
    uint32_t a;
    asm("{ .reg .u64 t; cvta.to.shared.u64 t, %1; cvt.u32.u64 %0, t; }" : "=r"(a) : "l"(p));
    return a;
}
__device__ __forceinline__ void ldm_x4(uint32_t* r, uint32_t addr) {
    asm volatile("ldmatrix.sync.aligned.m8n8.x4.shared.b16 {%0,%1,%2,%3}, [%4];"
        : "=r"(r[0]), "=r"(r[1]), "=r"(r[2]), "=r"(r[3]) : "r"(addr));
}
__device__ __forceinline__ void mma16816(float* d, const uint32_t* a, const uint32_t* b) {
    asm volatile(
        "mma.sync.aligned.m16n8k16.row.col.f32.f16.f16.f32 "
        "{%0,%1,%2,%3}, {%4,%5,%6,%7}, {%8,%9}, {%0,%1,%2,%3};"
        : "+f"(d[0]), "+f"(d[1]), "+f"(d[2]), "+f"(d[3])
        : "r"(a[0]), "r"(a[1]), "r"(a[2]), "r"(a[3]), "r"(b[0]), "r"(b[1]));
}
__device__ __forceinline__ void cp16(uint32_t dst, const void* src) {
    asm volatile("cp.async.ca.shared.global [%0], [%1], 16;" :: "r"(dst), "l"(src));
}
__device__ __forceinline__ void cp_commit() { asm volatile("cp.async.commit_group;"); }
__device__ __forceinline__ void cp_wait0()  { asm volatile("cp.async.wait_group 0;"); }

// smem: fp16, BK=64, row stride 72 elems (144B; +4 banks/row -> ldmatrix conflict-free)
#define LDS   72
#define TILEB 18432            // 128*72*2 bytes
#define OFF_A(s) ((s)*TILEB)
#define OFF_B(s) ((2+(s))*TILEB)
#define SMEM_GEMM  73728

// C[M,Nfull](@ldc,coff) fp16 = act( rowscale(A) @ B^T + bias_eff )
// A fp16, B fp16 [N,K] expert-stacked; gate!=null: A rows scaled per expert
// (LDG+scale+STS path), acc over experts, gated bias. Non-gated: pure cp.async.
__global__ __launch_bounds__(256) void mma_gemm(
    const __half* __restrict__ A, const __half* __restrict__ Bw,
    const float* __restrict__ bias, const float* __restrict__ gate,
    __half* __restrict__ C,
    int K, int ldc, int coff, int nexp, int relu)
{
    extern __shared__ char smc[];
    __shared__ float sbias[NE*128];
    uint32_t smb = smem_u32(smc);
    int tid = threadIdx.x;
    int lane = tid & 31, warp = tid >> 5;
    int wm = warp >> 2, wn = warp & 3;          // 2x4 warps: 64x32 warp tile
    int m0 = blockIdx.x * 128, n0 = blockIdx.y * 128;
    int Nfull = gridDim.y * 128;
    size_t bstride = (size_t)Nfull * K;

    for (int i = tid; i < nexp*128; i += 256)
        sbias[i] = bias[(size_t)(i >> 7) * Nfull + n0 + (i & 127)];

    float acc[4][4][4];
    #pragma unroll
    for (int mi = 0; mi < 4; mi++)
        #pragma unroll
        for (int ni = 0; ni < 4; ni++)
            #pragma unroll
            for (int q = 0; q < 4; q++) acc[mi][ni][q] = 0.f;

    const int tiles = K >> 6;                   // BK = 64
    const int T = nexp * tiles;

    // 16B chunk mapping: tile = 128 rows x 64 fp16 = 1024 chunks; 4 per thread
    int crow[4], ccol[4];
    #pragma unroll
    for (int i = 0; i < 4; i++) { int c = tid + i*256; crow[i] = c >> 3; ccol[i] = (c & 7) << 3; }

    uint4 ar[4]; float gv[4];

    auto load_async = [&](int s, int it2) {
        int e = it2 / tiles, k0 = (it2 - e*tiles) << 6;
        const __half* Bh = Bw + (size_t)e * bstride;
        #pragma unroll
        for (int i = 0; i < 4; i++) {
            uint32_t d = (uint32_t)(crow[i] * LDS + ccol[i]) * 2;
            cp16(smb + OFF_B(s) + d, &Bh[(size_t)(n0 + crow[i]) * K + k0 + ccol[i]]);
            if (!gate)
                cp16(smb + OFF_A(s) + d, &A[(size_t)(m0 + crow[i]) * K + k0 + ccol[i]]);
        }
        cp_commit();
    };
    auto load_a_regs = [&](int it2) {
        int e = it2 / tiles, k0 = (it2 - e*tiles) << 6;
        #pragma unroll
        for (int i = 0; i < 4; i++) {
            ar[i] = *(const uint4*)&A[(size_t)(m0 + crow[i]) * K + k0 + ccol[i]];
            gv[i] = gate[(size_t)(m0 + crow[i]) * 4 + e];
        }
    };
    auto store_a = [&](int s) {
        #pragma unroll
        for (int i = 0; i < 4; i++) {
            const uint32_t* pp = (const uint32_t*)&ar[i];
            uint32_t o[4];
            #pragma unroll
            for (int q = 0; q < 4; q++) {
                __half2 h2 = *(const __half2*)&pp[q];
                float2 f = __half22float2(h2);
                __half2 r = __floats2half2_rn(f.x * gv[i], f.y * gv[i]);
                o[q] = *(const uint32_t*)&r;
            }
            uint32_t d = (uint32_t)(crow[i] * LDS + ccol[i]) * 2;
            *(uint4*)(smc + OFF_A(s) + d) = make_uint4(o[0], o[1], o[2], o[3]);
        }
    };

    // prologue
    load_async(0, 0);
    if (gate) { load_a_regs(0); store_a(0); }
    cp_wait0();
    __syncthreads();

    for (int it = 0; it < T; it++) {
        int s = it & 1, ns = s ^ 1;
        if (it + 1 < T) {
            load_async(ns, it + 1);
            if (gate) load_a_regs(it + 1);
        }

        uint32_t aS = smb + OFF_A(s), bS = smb + OFF_B(s);
        #pragma unroll
        for (int ks = 0; ks < 4; ks++) {          // 4 x K16 within BK=64
            uint32_t bh[4][2], r4[4];
            #pragma unroll
            for (int np = 0; np < 2; np++) {
                uint32_t off = (uint32_t)((wn*32 + np*16 + (lane & 15)) * LDS
                                          + ks*16 + (lane >> 4)*8) * 2;
                ldm_x4(r4, bS + off);
                bh[np*2+0][0] = r4[0]; bh[np*2+0][1] = r4[2];
                bh[np*2+1][0] = r4[1]; bh[np*2+1][1] = r4[3];
            }
            uint32_t ah[4][4];
            #pragma unroll
            for (int mi = 0; mi < 4; mi++) {
                uint32_t off = (uint32_t)((wm*64 + mi*16 + (lane & 15)) * LDS
                                          + ks*16 + (lane >> 4)*8) * 2;
                ldm_x4(ah[mi], aS + off);
            }
            #pragma unroll
            for (int mi = 0; mi < 4; mi++)
                #pragma unroll
                for (int ni = 0; ni < 4; ni++)
                    mma16816(acc[mi][ni], ah[mi], bh[ni]);
        }
        if (it + 1 < T) {
            if (gate) store_a(ns);
            cp_wait0();
        }
        __syncthreads();
    }

    // epilogue: fp16 C, gated bias
    #pragma unroll
    for (int mi = 0; mi < 4; mi++) {
        #pragma unroll
        for (int sub = 0; sub < 2; sub++) {
            int row = m0 + wm*64 + mi*16 + (lane >> 2) + sub*8;
            float4 g4 = make_float4(0.f, 0.f, 0.f, 0.f);
            if (gate) g4 = *(const float4*)&gate[(size_t)row * 4];
            #pragma unroll
            for (int ni = 0; ni < 4; ni++) {
                int cl = wn*32 + ni*8 + (lane & 3)*2;
                float be0, be1;
                if (gate) {
                    be0 = g4.x*sbias[cl]     + g4.y*sbias[128+cl]
                        + g4.z*sbias[256+cl] + g4.w*sbias[384+cl];
                    be1 = g4.x*sbias[cl+1]     + g4.y*sbias[128+cl+1]
                        + g4.z*sbias[256+cl+1] + g4.w*sbias[384+cl+1];
                } else { be0 = sbias[cl]; be1 = sbias[cl+1]; }
                float v0 = acc[mi][ni][sub*2+0] + be0;
                float v1 = acc[mi][ni][sub*2+1] + be1;
                if (relu) { v0 = fmaxf(v0, 0.f); v1 = fmaxf(v1, 0.f); }
                *(__half2*)&C[(size_t)row * ldc + coff + n0 + cl] = __floats2half2_rn(v0, v1);
            }
        }
    }
}

// ---------------- enc3 ----------------
__global__ __launch_bounds__(256) void enc3_kernel(
    const float* __restrict__ cx, const float* __restrict__ cy,
    const float* __restrict__ Wp, const float* __restrict__ bp,
    const float* __restrict__ Wl, const float* __restrict__ bl)
{
    __shared__ float red[256*9];
    __shared__ float h0[HID];
    int b = blockIdx.x, tid = threadIdx.x;
    float l[9];
    #pragma unroll
    for (int x = 0; x < 9; x++) l[x] = 0.f;
    for (int c = tid; c < NC; c += 256) {
        #pragma unroll
        for (int x = 0; x < XD; x++) l[x] += cx[((size_t)b*NC + c)*XD + x];
        l[8] += cy[b*NC + c];
    }
    #pragma unroll
    for (int x = 0; x < 9; x++) red[tid*9 + x] = l[x];
    __syncthreads();
    for (int s = 128; s; s >>= 1) {
        if (tid < s) {
            #pragma unroll
            for (int x = 0; x < 9; x++) red[tid*9 + x] += red[(tid+s)*9 + x];
        }
        __syncthreads();
    }
    {
        int h = tid;
        float a = bp[h];
        #pragma unroll
        for (int x = 0; x < 9; x++) a = fmaf(red[x]*(1.f/NC), Wp[x*HID + h], a);
        h0[h] = a;
    }
    __syncthreads();
    {
        int h = tid;
        float a = bl[h];
        for (int k = 0; k < HID; k++) a = fmaf(h0[k], Wl[k*HID + h], a);
        g_enc3[b*HID + h] = a;
    }
}

// ---------------- per-target encoder (writes fp16 activations) ----------------
__global__ __launch_bounds__(256) void target_kernel(
    const float* __restrict__ cx, const float* __restrict__ cy,
    const float* __restrict__ txg,
    const float* __restrict__ Wee, const float* __restrict__ bee,
    const float* __restrict__ Wge, const float* __restrict__ bge,
    const float* __restrict__ Wat, const float* __restrict__ bat)
{
    extern __shared__ float smf[];
    float* sc  = smf;
    float* sWe = sc  + NC*9;
    float* sbe = sWe + NE*9*HID;
    float* sWa = sbe + NE*HID;
    float* sba = sWa + XD*HH;
    float* sWg = sba + HH;
    float* sbg = sWg + XD*NE;

    int b  = blockIdx.x >> 4;
    int t0 = (blockIdx.x & 15) << 7;
    int tid = threadIdx.x;

    for (int i = tid; i < NC*XD; i += 256) sc[(i>>3)*9 + (i&7)] = cx[(size_t)b*NC*XD + i];
    for (int i = tid; i < NC;    i += 256) sc[i*9 + 8] = cy[b*NC + i];
    for (int i = tid; i < NE*9*HID; i += 256) sWe[i] = Wee[i];
    for (int i = tid; i < NE*HID;   i += 256) sbe[i] = bee[i];
    for (int i = tid; i < XD*HH;    i += 256) sWa[i] = Wat[i];
    if (tid < HH)    sba[tid] = bat[tid];
    if (tid < XD*NE) sWg[tid] = Wge[tid];
    if (tid < NE)    sbg[tid] = bge[tid];
    __syncthreads();

    int warp = tid >> 5, lane = tid & 31;
    for (int tt = warp; tt < 128; tt += 8) {
        int t = t0 + tt;
        size_t gt = (size_t)b*NT + t;
        float tx[XD];
        #pragma unroll
        for (int x = 0; x < XD; x++) tx[x] = txg[gt*XD + x];

        float acc[10];
        #pragma unroll
        for (int i = 0; i < 10; i++) acc[i] = 0.f;
        for (int c = lane; c < NC; c += 32) {
            const float* p = &sc[c*9];
            float d2 = 1e-12f;
            #pragma unroll
            for (int x = 0; x < XD; x++) { float d = tx[x]-p[x]; d2 = fmaf(d, d, d2); }
            float dist = d2 * __frsqrt_rn(d2);
            float w = __expf(-dist);
            acc[9] += w;
            #pragma unroll
            for (int x = 0; x < 9; x++) acc[x] = fmaf(w, p[x], acc[x]);
        }
        #pragma unroll
        for (int o = 16; o; o >>= 1) {
            #pragma unroll
            for (int i = 0; i < 10; i++) acc[i] += __shfl_xor_sync(0xffffffffu, acc[i], o);
        }
        float inv = 1.f/acc[9];
        float s[9];
        #pragma unroll
        for (int x = 0; x < 9; x++) s[x] = acc[x]*inv;

        float g[NE];
        #pragma unroll
        for (int e = 0; e < NE; e++) {
            float a = sbg[e];
            #pragma unroll
            for (int x = 0; x < XD; x++) a = fmaf(tx[x], sWg[x*NE + e], a);
            g[e] = a;
        }
        float gm = fmaxf(fmaxf(g[0],g[1]), fmaxf(g[2],g[3]));
        float gs = 0.f;
        #pragma unroll
        for (int e = 0; e < NE; e++) { g[e] = __expf(g[e]-gm); gs += g[e]; }
        float gi = 1.f/gs;
        #pragma unroll
        for (int e = 0; e < NE; e++) g[e] *= gi;

        #pragma unroll
        for (int j = 0; j < 8; j++) {
            int h = lane + 32*j;
            float o2 = 0.f;
            #pragma unroll
            for (int e = 0; e < NE; e++) {
                float a = sbe[e*HID + h];
                #pragma unroll
                for (int x = 0; x < 9; x++) a = fmaf(s[x], sWe[(e*9 + x)*HID + h], a);
                o2 = fmaf(g[e], a, o2);
            }
            g_z[gt*512 + 256 + h] = __float2half_rn(o2);
            g_z[gt*512 + h] = __float2half_rn(g_enc3[b*HID + h]);
        }
        #pragma unroll
        for (int j = 0; j < 4; j++) {
            int h = lane + 32*j;
            float a = sba[h];
            #pragma unroll
            for (int x = 0; x < XD; x++) a = fmaf(tx[x], sWa[x*HH + h], a);
            g_zd[gt*DD + h] = __float2half_rn(a);
        }
    }
}

// ---------------- decoder gate ----------------
__global__ __launch_bounds__(256) void decgate_kernel(
    const float* __restrict__ Wg, const float* __restrict__ bg)
{
    int warp = threadIdx.x >> 5, lane = threadIdx.x & 31;
    size_t gt = (size_t)blockIdx.x*8 + warp;
    float a0=0.f, a1=0.f, a2=0.f, a3=0.f;
    const float4* W4 = (const float4*)Wg;
    for (int k = lane; k < DD; k += 32) {
        float z = __half2float(g_zd[gt*DD + k]);
        float4 w = W4[k];
        a0 = fmaf(z, w.x, a0); a1 = fmaf(z, w.y, a1);
        a2 = fmaf(z, w.z, a2); a3 = fmaf(z, w.w, a3);
    }
    #pragma unroll
    for (int o = 16; o; o >>= 1) {
        a0 += __shfl_xor_sync(0xffffffffu, a0, o);
        a1 += __shfl_xor_sync(0xffffffffu, a1, o);
        a2 += __shfl_xor_sync(0xffffffffu, a2, o);
        a3 += __shfl_xor_sync(0xffffffffu, a3, o);
    }
    a0 += bg[0]; a1 += bg[1]; a2 += bg[2]; a3 += bg[3];
    float m = fmaxf(fmaxf(a0,a1), fmaxf(a2,a3));
    float e0 = __expf(a0-m), e1 = __expf(a1-m), e2 = __expf(a2-m), e3 = __expf(a3-m);
    float inv = 1.f/(e0+e1+e2+e3);
    if (lane == 0) {
        g_gd[gt*4+0] = e0*inv; g_gd[gt*4+1] = e1*inv;
        g_gd[gt*4+2] = e2*inv; g_gd[gt*4+3] = e3*inv;
    }
}

// ---------------- head ----------------
__global__ __launch_bounds__(256) void head_kernel(
    const float* __restrict__ W3, const float* __restrict__ b3, float* __restrict__ out)
{
    int warp = threadIdx.x >> 5, lane = threadIdx.x & 31;
    size_t gt = (size_t)blockIdx.x*8 + warp;
    float a0=0.f, a1=0.f;
    const float2* W2 = (const float2*)W3;
    for (int k = lane; k < HID; k += 32) {
        float h = __half2float(g_h2[gt*HID + k]);
        float2 w = W2[k];
        a0 = fmaf(h, w.x, a0); a1 = fmaf(h, w.y, a1);
    }
    #pragma unroll
    for (int o = 16; o; o >>= 1) {
        a0 += __shfl_xor_sync(0xffffffffu, a0, o);
        a1 += __shfl_xor_sync(0xffffffffu, a1, o);
    }
    if (lane == 0) {
        float mu = a0 + b3[0];
        float x  = a1 + b3[1];
        float sp = fmaxf(x, 0.f) + log1pf(__expf(-fabsf(x)));
        out[gt]       = mu;
        out[NTT + gt] = 0.1f + 0.9f*sp;
    }
}

// ---------------- Moran k-NN lag ----------------
__global__ __launch_bounds__(256) void moran_kernel(
    const float* __restrict__ txg, const float* __restrict__ tyg, float* __restrict__ out)
{
    extern __shared__ float smf[];
    float* st  = smf;
    float* sy  = st + NT*9;
    float* smu = sy + NT;
    int b  = blockIdx.x >> 4;
    int t0 = (blockIdx.x & 15) << 7;
    int tid = threadIdx.x;

    for (int i = tid; i < NT*XD; i += 256) st[(i>>3)*9 + (i&7)] = txg[(size_t)b*NT*XD + i];
    for (int i = tid; i < NT; i += 256) { sy[i] = tyg[b*NT + i]; smu[i] = out[b*NT + i]; }
    __syncthreads();
    for (int i = tid; i < NT; i += 256) {
        float n = 0.f;
        #pragma unroll
        for (int x = 0; x < XD; x++) { float v = st[i*9 + x]; n = fmaf(v, v, n); }
        st[i*9 + 8] = n;
    }
    __syncthreads();

    int warp = tid >> 5, lane = tid & 31;
    for (int tt = warp; tt < 128; tt += 8) {
        int t = t0 + tt;
        float tx[XD];
        #pragma unroll
        for (int x = 0; x < XD; x++) tx[x] = st[t*9 + x];
        float tn = st[t*9 + 8];

        float bd0=INFINITY,bd1=INFINITY,bd2=INFINITY,bd3=INFINITY,bd4=INFINITY;
        int   bi0=0,bi1=0,bi2=0,bi3=0,bi4=0;
        for (int c = lane; c < NT; c += 32) {
            if (c == t) continue;
            const float* p = &st[c*9];
            float dot = 0.f;
            #pragma unroll
            for (int x = 0; x < XD; x++) dot = fmaf(tx[x], p[x], dot);
            float d2 = tn + p[8] - 2.f*dot;
            d2 = fmaxf(d2, 0.f) + 1e-12f;
            if (d2 < bd4) {
                bd4 = d2; bi4 = c;
                if (bd4 < bd3) { float td=bd3; bd3=bd4; bd4=td; int ti=bi3; bi3=bi4; bi4=ti; }
                if (bd3 < bd2) { float td=bd2; bd2=bd3; bd3=td; int ti=bi2; bi2=bi3; bi3=ti; }
                if (bd2 < bd1) { float td=bd1; bd1=bd2; bd2=td; int ti=bi1; bi1=bi2; bi2=ti; }
                if (bd1 < bd0) { float td=bd0; bd0=bd1; bd1=td; int ti=bi0; bi0=bi1; bi1=ti; }
            }
        }
        float seld[5]; int seli[5];
        #pragma unroll
        for (int r = 0; r < 5; r++) {
            float rd = bd0; int ri = bi0; int rl = lane;
            #pragma unroll
            for (int o = 16; o; o >>= 1) {
                float od = __shfl_xor_sync(0xffffffffu, rd, o);
                int   oi = __shfl_xor_sync(0xffffffffu, ri, o);
                int   ol = __shfl_xor_sync(0xffffffffu, rl, o);
                if (od < rd || (od == rd && oi < ri)) { rd = od; ri = oi; rl = ol; }
            }
            seld[r] = rd; seli[r] = ri;
            if (lane == rl) {
                bd0=bd1; bi0=bi1; bd1=bd2; bi1=bi2; bd2=bd3; bi2=bi3;
                bd3=bd4; bi3=bi4; bd4=INFINITY; bi4=0x7fffffff;
            }
        }
        if (lane == 0) {
            float w[5], ws = 0.f;
            #pragma unroll
            for (int r = 0; r < 5; r++) { w[r] = __expf(-0.1f*sqrtf(seld[r])); ws += w[r]; }
            float inv = 1.f/ws;
            float ly = 0.f, lm = 0.f;
            #pragma unroll
            for (int r = 0; r < 5; r++) {
                float wr = w[r]*inv;
                ly = fmaf(wr, sy[seli[r]],  ly);
                lm = fmaf(wr, smu[seli[r]], lm);
            }
            size_t gt = (size_t)b*NT + t;
            out[2*(size_t)NTT + gt] = ly;
            out[3*(size_t)NTT + gt] = lm;
        }
    }
}

// ---------------- launch ----------------
extern "C" void kernel_launch(void* const* d_in, const int* in_sizes, int n_in,
                              void* d_out, int out_size)
{
    const float* cx   = (const float*)d_in[0];
    const float* cy   = (const float*)d_in[1];
    const float* txp  = (const float*)d_in[2];
    const float* typ  = (const float*)d_in[3];
    const float* Wge  = (const float*)d_in[4];
    const float* bge  = (const float*)d_in[5];
    const float* Wee  = (const float*)d_in[6];
    const float* bee  = (const float*)d_in[7];
    const float* Wp3  = (const float*)d_in[8];
    const float* bp3  = (const float*)d_in[9];
    const float* Wlin = (const float*)d_in[10];
    const float* blin = (const float*)d_in[11];
    const float* Wf1  = (const float*)d_in[12];
    const float* bf1  = (const float*)d_in[13];
    const float* Wf2  = (const float*)d_in[14];
    const float* bf2  = (const float*)d_in[15];
    const float* Wat  = (const float*)d_in[16];
    const float* bat  = (const float*)d_in[17];
    const float* Wgd  = (const float*)d_in[18];
    const float* bgd  = (const float*)d_in[19];
    const float* Wed  = (const float*)d_in[20];
    const float* bed  = (const float*)d_in[21];
    const float* Wd1  = (const float*)d_in[22];
    const float* bd1  = (const float*)d_in[23];
    const float* Wd2  = (const float*)d_in[24];
    const float* bd2  = (const float*)d_in[25];
    const float* Wd3  = (const float*)d_in[26];
    const float* bd3  = (const float*)d_in[27];
    float* out = (float*)d_out;

    float *p_gd;
    cudaGetSymbolAddress((void**)&p_gd, g_gd);
    __half *p_z, *p_fh, *p_zd, *p_zd2, *p_h1, *p_h2;
    cudaGetSymbolAddress((void**)&p_z,   g_z);
    cudaGetSymbolAddress((void**)&p_fh,  g_fh);
    cudaGetSymbolAddress((void**)&p_zd,  g_zd);
    cudaGetSymbolAddress((void**)&p_zd2, g_zd2);
    cudaGetSymbolAddress((void**)&p_h1,  g_h1);
    cudaGetSymbolAddress((void**)&p_h2,  g_h2);
    __half *wf1, *wf2, *wm, *wd1, *wd2;
    cudaGetSymbolAddress((void**)&wf1, g_wf1);
    cudaGetSymbolAddress((void**)&wf2, g_wf2);
    cudaGetSymbolAddress((void**)&wm,  g_wm);
    cudaGetSymbolAddress((void**)&wd1, g_wd1);
    cudaGetSymbolAddress((void**)&wd2, g_wd2);

    const int smem_t = (NC*9 + NE*9*HID + NE*HID + XD*HH + HH + XD*NE + NE)*4;
    const int smem_m = (NT*9 + NT + NT)*4;
    cudaFuncSetAttribute(target_kernel, cudaFuncAttributeMaxDynamicSharedMemorySize, smem_t);
    cudaFuncSetAttribute(moran_kernel,  cudaFuncAttributeMaxDynamicSharedMemorySize, smem_m);
    cudaFuncSetAttribute(mma_gemm,      cudaFuncAttributeMaxDynamicSharedMemorySize, SMEM_GEMM);

    PrepDesc pd0 = { Wf1, wf1, 512, 128, 512*128 };
    PrepDesc pd1 = { Wf2, wf2, 128, 256, 128*256 };
    PrepDesc pd2 = { Wed, wm,  384, 384, 4*384*384 };
    PrepDesc pd3 = { Wd1, wd1, 384, 256, 384*256 };
    PrepDesc pd4 = { Wd2, wd2, 256, 256, 256*256 };
    prep_all<<<dim3(160, 5), 256>>>(pd0, pd1, pd2, pd3, pd4);

    enc3_kernel<<<BSZ, 256>>>(cx, cy, Wp3, bp3, Wlin, blin);
    target_kernel<<<256, 256, smem_t>>>(cx, cy, txp, Wee, bee, Wge, bge, Wat, bat);
    // fps1: relu(z @ Wf1 + b)
    mma_gemm<<<dim3(256,1), 256, SMEM_GEMM>>>(p_z,   wf1, bf1, nullptr, p_fh,  512, 128, 0,   1, 1);
    // fps2: r = fh @ Wf2 + b -> zd[:,128:384]
    mma_gemm<<<dim3(256,2), 256, SMEM_GEMM>>>(p_fh,  wf2, bf2, nullptr, p_zd,  128, 384, 128, 1, 0);
    decgate_kernel<<<NTT/8, 256>>>(Wgd, bgd);
    // decoder MoE (gate-scaled A rows, accumulate over experts)
    mma_gemm<<<dim3(256,3), 256, SMEM_GEMM>>>(p_zd,  wm,  bed, p_gd,    p_zd2, 384, 384, 0,   4, 0);
    mma_gemm<<<dim3(256,2), 256, SMEM_GEMM>>>(p_zd2, wd1, bd1, nullptr, p_h1,  384, 256, 0,   1, 1);
    mma_gemm<<<dim3(256,2), 256, SMEM_GEMM>>>(p_h1,  wd2, bd2, nullptr, p_h2,  256, 256, 0,   1, 1);
    head_kernel<<<NTT/8, 256>>>(Wd3, bd3, out);
    moran_kernel<<<256, 256, smem_m>>>(txp, typ, out);
}